// round 1
// baseline (speedup 1.0000x reference)
#include <cuda_runtime.h>

// GraphSage fused 2-layer kernel for GB300 (sm_103a).
// Layer1: h1 = concat(features, mean(features[nbr])) @ w1   for ALL N nodes
// Layer2: out = concat(h1[nodes], mean(h1[nbr[nodes]])) @ w2 for B batch nodes
//
// Strategy: fp32x2 packed FFMA (FFMA2) register-tiled GEMM with the concat
// input built in shared memory. Both layers use the same templated kernel.

#define F        128
#define H        128
#define DEG      16
#define KDIM     256          // 2*F
#define TILE     64           // rows per block
#define THREADS  256
#define XPITCH   260          // KDIM + 4 pad (keeps float4 alignment, kills conflicts)

// Scratch for layer-1 embeddings (static __device__ array: allocation-free).
// Sized generously in case N varies slightly.
__device__ float g_h1[131072 * 128];

typedef unsigned long long u64;

__device__ __forceinline__ u64 pk2(float lo, float hi) {
    u64 r; asm("mov.b64 %0, {%1, %2};" : "=l"(r) : "f"(lo), "f"(hi)); return r;
}
__device__ __forceinline__ void upk2(u64 v, float& lo, float& hi) {
    asm("mov.b64 {%0, %1}, %2;" : "=f"(lo), "=f"(hi) : "l"(v));
}
__device__ __forceinline__ u64 ffma2(u64 a, u64 b, u64 c) {
    u64 d; asm("fma.rn.f32x2 %0, %1, %2, %3;" : "=l"(d) : "l"(a), "l"(b), "l"(c)); return d;
}

// LAYER2=false: src=features, row ids are block-linear, out=g_h1 [N,128]
// LAYER2=true : src=g_h1, row ids come from nodes[], out=d_out [B,128]
template<bool LAYER2>
__global__ void __launch_bounds__(THREADS, 1) sage_kernel(
    const float* __restrict__ src,
    const float* __restrict__ w,            // [KDIM, H] row-major
    const int*   __restrict__ neighbor_idx, // [N, DEG]
    const int*   __restrict__ nodes,        // [B] (layer2 only)
    float*       __restrict__ out,
    int nRows)
{
    extern __shared__ float smem[];
    float* x_s = smem;                        // [TILE][XPITCH]
    float* w_s = smem + TILE * XPITCH;        // [KDIM][H]
    __shared__ int nb_s[TILE * DEG];
    __shared__ int self_s[TILE];

    const int tid  = threadIdx.x;
    const int base = blockIdx.x * TILE;

    // ---- stage weights (coalesced float4 copy; L2-resident source) ----
    {
        const float4* w4  = (const float4*)w;
        float4*       ws4 = (float4*)w_s;
        #pragma unroll 4
        for (int i = tid; i < (KDIM * H) / 4; i += THREADS) ws4[i] = w4[i];
    }
    // ---- stage self row ids ----
    for (int i = tid; i < TILE; i += THREADS) {
        int r = base + i;
        int g = 0;
        if (r < nRows) g = LAYER2 ? nodes[r] : r;
        self_s[i] = g;
    }
    __syncthreads();
    // ---- stage neighbor ids ----
    for (int i = tid; i < TILE * DEG; i += THREADS) {
        int node = i >> 4, d = i & 15;
        nb_s[i] = neighbor_idx[(size_t)self_s[node] * DEG + d];
    }
    __syncthreads();

    // ---- build x tile: [self_features | mean(neighbor_features)] ----
    // Each (node, k0) unit: warp covers one full 512B source row -> coalesced.
    for (int i = tid; i < TILE * (F / 4); i += THREADS) {
        int node = i >> 5;
        int k0   = (i & 31) * 4;
        const float4 sv = *(const float4*)(src + (size_t)self_s[node] * F + k0);
        *(float4*)&x_s[node * XPITCH + k0] = sv;

        float ax = 0.f, ay = 0.f, az = 0.f, aw = 0.f;
        const int* nb = &nb_s[node * DEG];
        #pragma unroll
        for (int d = 0; d < DEG; d++) {
            const float4 v = *(const float4*)(src + (size_t)nb[d] * F + k0);
            ax += v.x; ay += v.y; az += v.z; aw += v.w;
        }
        float4 av;
        av.x = ax * 0.0625f; av.y = ay * 0.0625f;
        av.z = az * 0.0625f; av.w = aw * 0.0625f;
        *(float4*)&x_s[node * XPITCH + F + k0] = av;
    }
    __syncthreads();

    // ---- register-tiled GEMM: 8 rows x 4 cols per thread, f32x2 packed ----
    const int tx   = tid & 31;        // 32 col-groups of 4 -> 128 cols
    const int ty   = tid >> 5;        // 8 row-groups of 8 -> 64 rows
    const int col  = tx * 4;
    const int row0 = ty * 8;

    u64 acc[8][2];
    #pragma unroll
    for (int n = 0; n < 8; n++) { acc[n][0] = 0ULL; acc[n][1] = 0ULL; }

    const float* xb = &x_s[row0 * XPITCH];

    for (int k0 = 0; k0 < KDIM; k0 += 4) {
        u64 wb[4][2];
        #pragma unroll
        for (int ki = 0; ki < 4; ki++) {
            const float4 wv = *(const float4*)&w_s[(k0 + ki) * H + col];
            wb[ki][0] = pk2(wv.x, wv.y);
            wb[ki][1] = pk2(wv.z, wv.w);
        }
        #pragma unroll
        for (int n = 0; n < 8; n++) {
            const float4 xv = *(const float4*)&xb[n * XPITCH + k0];  // warp-uniform -> broadcast
            u64 xa;
            xa = pk2(xv.x, xv.x);
            acc[n][0] = ffma2(xa, wb[0][0], acc[n][0]);
            acc[n][1] = ffma2(xa, wb[0][1], acc[n][1]);
            xa = pk2(xv.y, xv.y);
            acc[n][0] = ffma2(xa, wb[1][0], acc[n][0]);
            acc[n][1] = ffma2(xa, wb[1][1], acc[n][1]);
            xa = pk2(xv.z, xv.z);
            acc[n][0] = ffma2(xa, wb[2][0], acc[n][0]);
            acc[n][1] = ffma2(xa, wb[2][1], acc[n][1]);
            xa = pk2(xv.w, xv.w);
            acc[n][0] = ffma2(xa, wb[3][0], acc[n][0]);
            acc[n][1] = ffma2(xa, wb[3][1], acc[n][1]);
        }
    }

    // ---- epilogue: output row = block-linear index for both layers ----
    #pragma unroll
    for (int n = 0; n < 8; n++) {
        int r = base + row0 + n;
        if (r < nRows) {
            float4 o;
            upk2(acc[n][0], o.x, o.y);
            upk2(acc[n][1], o.z, o.w);
            *(float4*)&out[(size_t)r * H + col] = o;
        }
    }
}

extern "C" void kernel_launch(void* const* d_in, const int* in_sizes, int n_in,
                              void* d_out, int out_size)
{
    const float* features     = (const float*)d_in[0];
    const float* w1           = (const float*)d_in[1];
    const float* w2           = (const float*)d_in[2];
    const int*   neighbor_idx = (const int*)d_in[3];
    const int*   nodes        = (const int*)d_in[4];
    float*       out          = (float*)d_out;

    const int N = in_sizes[0] / F;
    const int B = in_sizes[4];

    float* h1;
    cudaGetSymbolAddress((void**)&h1, g_h1);

    const int smem = (TILE * XPITCH + KDIM * H) * (int)sizeof(float);  // 197632 B
    cudaFuncSetAttribute(sage_kernel<false>,
                         cudaFuncAttributeMaxDynamicSharedMemorySize, smem);
    cudaFuncSetAttribute(sage_kernel<true>,
                         cudaFuncAttributeMaxDynamicSharedMemorySize, smem);

    // Layer 1: h1 for all N nodes
    sage_kernel<false><<<(N + TILE - 1) / TILE, THREADS, smem>>>(
        features, w1, neighbor_idx, nodes, h1, N);
    // Layer 2: output for B batch nodes
    sage_kernel<true><<<(B + TILE - 1) / TILE, THREADS, smem>>>(
        h1, w2, neighbor_idx, nodes, out, B);
}

// round 3
// speedup vs baseline: 1.2723x; 1.2723x over previous
#include <cuda_runtime.h>
#include <cuda_bf16.h>
#include <cuda_fp16.h>
#include <cstdint>

#define F      128
#define H      128
#define DEG    16
#define KDIM   256
#define NMAX   131072
#define PITCH  136            // bf16 elems per smem row; 272B = 68 words ≡ 4 (mod 32) -> conflict-free frags

// ---------------- scratch (static __device__: allocation-free) ----------------
__device__ float         g_Yt[(size_t)NMAX * 128];     // f @ w1_top  (fp32)
__device__ __half        g_Yb[(size_t)NMAX * 128];     // f @ w1_bot  (fp16, gathered)
__device__ float         g_h1[(size_t)NMAX * 128];     // layer-1 embeddings
__device__ __nv_bfloat16 g_Bimg[2][2][128 * PITCH];    // [ch][lvl] pre-split, padded B tiles

// ---------------- mma.sync helper (sm_80+ PTX, works at compute_103) ----------------
__device__ __forceinline__ void mma16816(float* c, const uint32_t* a, const uint32_t* b) {
    asm volatile(
        "mma.sync.aligned.m16n8k16.row.col.f32.bf16.bf16.f32 "
        "{%0,%1,%2,%3}, {%4,%5,%6,%7}, {%8,%9}, {%0,%1,%2,%3};"
        : "+f"(c[0]), "+f"(c[1]), "+f"(c[2]), "+f"(c[3])
        : "r"(a[0]), "r"(a[1]), "r"(a[2]), "r"(a[3]), "r"(b[0]), "r"(b[1]));
}

// ---------------- kernel 1: build padded bf16 hi/lo B images ----------------
// B[ch][n][k] = w1[ch*128 + k][n]  (so gemm block copies linearly, no transpose)
__global__ void prep_w_kernel(const float* __restrict__ w1) {
    int i = blockIdx.x * 256 + threadIdx.x;          // 2*128*128 = 32768
    if (i >= 2 * 128 * 128) return;
    int ch = i >> 14;
    int n  = (i >> 7) & 127;
    int k  = i & 127;
    float v = w1[(size_t)(ch * 128 + k) * 128 + n];
    __nv_bfloat16 hi = __float2bfloat16_rn(v);
    __nv_bfloat16 lo = __float2bfloat16_rn(v - __bfloat162float(hi));
    g_Bimg[ch][0][n * PITCH + k] = hi;
    g_Bimg[ch][1][n * PITCH + k] = lo;
}

// ---------------- kernel 2: persistent bf16x3 mma.sync GEMM ----------------
// Y[:,0:128]=f@w1_top -> Yt (fp32);  Y[:,128:256]=f@w1_bot -> Yb (fp16)
// Block: 256 thr (8 warps, 4m x 2n), tile 128 rows x 128 cols (col-half = blockIdx.y)
#define AH_OFF 0
#define AL_OFF (128 * PITCH * 2)
#define BH_OFF (2 * 128 * PITCH * 2)
#define BL_OFF (3 * 128 * PITCH * 2)
#define SMEM_GEMM (4 * 128 * PITCH * 2)   // 139264 B

__global__ void __launch_bounds__(256, 1) gemm1_kernel(
    const float* __restrict__ f, float* __restrict__ Yt, __half* __restrict__ Yb,
    int nRows, int nTiles)
{
    extern __shared__ unsigned char smem[];
    const int tid = threadIdx.x, wid = tid >> 5, lid = tid & 31;
    const int ch  = blockIdx.y;
    const int g   = lid >> 2, tig = lid & 3;
    const int warp_m = wid & 3, warp_n = wid >> 2;

    // stage B once (linear copy of pre-built image: hi then lo, contiguous)
    {
        const uint4* src = (const uint4*)&g_Bimg[ch][0][0];
        uint4* dst = (uint4*)(smem + BH_OFF);
        #pragma unroll 4
        for (int i = tid; i < 2 * 128 * PITCH * 2 / 16; i += 256) dst[i] = src[i];
    }

    for (int t = blockIdx.x; t < nTiles; t += gridDim.x) {
        const int base = t * 128;

        // ---- stage A tile: fp32 -> bf16 hi/lo, row-major pitch-136 ----
        for (int i = tid; i < 128 * 32; i += 256) {
            int r  = i >> 5;
            int k0 = (i & 31) * 4;
            uint2 uh = make_uint2(0u, 0u), ul = make_uint2(0u, 0u);
            int grow = base + r;
            if (grow < nRows) {
                float4 v = *(const float4*)(f + (size_t)grow * 128 + k0);
                __nv_bfloat16 h0 = __float2bfloat16_rn(v.x);
                __nv_bfloat16 h1v = __float2bfloat16_rn(v.y);
                __nv_bfloat16 h2 = __float2bfloat16_rn(v.z);
                __nv_bfloat16 h3 = __float2bfloat16_rn(v.w);
                __nv_bfloat16 l0 = __float2bfloat16_rn(v.x - __bfloat162float(h0));
                __nv_bfloat16 l1 = __float2bfloat16_rn(v.y - __bfloat162float(h1v));
                __nv_bfloat16 l2 = __float2bfloat16_rn(v.z - __bfloat162float(h2));
                __nv_bfloat16 l3 = __float2bfloat16_rn(v.w - __bfloat162float(h3));
                uh.x = ((uint32_t)__bfloat16_as_ushort(h1v) << 16) | __bfloat16_as_ushort(h0);
                uh.y = ((uint32_t)__bfloat16_as_ushort(h3)  << 16) | __bfloat16_as_ushort(h2);
                ul.x = ((uint32_t)__bfloat16_as_ushort(l1)  << 16) | __bfloat16_as_ushort(l0);
                ul.y = ((uint32_t)__bfloat16_as_ushort(l3)  << 16) | __bfloat16_as_ushort(l2);
            }
            *(uint2*)(smem + AH_OFF + r * (PITCH * 2) + k0 * 2) = uh;
            *(uint2*)(smem + AL_OFF + r * (PITCH * 2) + k0 * 2) = ul;
        }
        __syncthreads();

        // ---- mma loop: 3 products x 8 k-steps; warp tile 32x64 ----
        float acc[2][8][4];
        #pragma unroll
        for (int mb = 0; mb < 2; mb++)
            #pragma unroll
            for (int nb = 0; nb < 8; nb++)
                #pragma unroll
                for (int q = 0; q < 4; q++) acc[mb][nb][q] = 0.f;

        #pragma unroll
        for (int p = 0; p < 3; p++) {
            const unsigned char* Ab = smem + ((p == 1) ? AL_OFF : AH_OFF);
            const unsigned char* Bb = smem + ((p == 2) ? BL_OFF : BH_OFF);
            #pragma unroll
            for (int ks = 0; ks < 8; ks++) {
                const int k0 = ks * 16;
                uint32_t a[2][4];
                #pragma unroll
                for (int mb = 0; mb < 2; mb++) {
                    int r0 = warp_m * 32 + mb * 16 + g;
                    const unsigned char* rp0 = Ab + r0 * (PITCH * 2);
                    const unsigned char* rp1 = Ab + (r0 + 8) * (PITCH * 2);
                    a[mb][0] = *(const uint32_t*)(rp0 + (k0 + tig * 2) * 2);
                    a[mb][1] = *(const uint32_t*)(rp1 + (k0 + tig * 2) * 2);
                    a[mb][2] = *(const uint32_t*)(rp0 + (k0 + tig * 2 + 8) * 2);
                    a[mb][3] = *(const uint32_t*)(rp1 + (k0 + tig * 2 + 8) * 2);
                }
                uint32_t b[8][2];
                #pragma unroll
                for (int nb = 0; nb < 8; nb++) {
                    int c0 = warp_n * 64 + nb * 8 + g;
                    const unsigned char* cp = Bb + c0 * (PITCH * 2);
                    b[nb][0] = *(const uint32_t*)(cp + (k0 + tig * 2) * 2);
                    b[nb][1] = *(const uint32_t*)(cp + (k0 + tig * 2 + 8) * 2);
                }
                #pragma unroll
                for (int mb = 0; mb < 2; mb++)
                    #pragma unroll
                    for (int nb = 0; nb < 8; nb++)
                        mma16816(acc[mb][nb], a[mb], b[nb]);
            }
        }

        // ---- epilogue ----
        #pragma unroll
        for (int mb = 0; mb < 2; mb++) {
            int row0 = base + warp_m * 32 + mb * 16 + g;
            #pragma unroll
            for (int nb = 0; nb < 8; nb++) {
                int col = warp_n * 64 + nb * 8 + tig * 2;
                if (ch == 0) {
                    if (row0 < nRows)
                        *(float2*)(Yt + (size_t)row0 * 128 + col) =
                            make_float2(acc[mb][nb][0], acc[mb][nb][1]);
                    if (row0 + 8 < nRows)
                        *(float2*)(Yt + (size_t)(row0 + 8) * 128 + col) =
                            make_float2(acc[mb][nb][2], acc[mb][nb][3]);
                } else {
                    if (row0 < nRows) {
                        __half2 hv = __floats2half2_rn(acc[mb][nb][0], acc[mb][nb][1]);
                        *(__half2*)(Yb + (size_t)row0 * 128 + col) = hv;
                    }
                    if (row0 + 8 < nRows) {
                        __half2 hv = __floats2half2_rn(acc[mb][nb][2], acc[mb][nb][3]);
                        *(__half2*)(Yb + (size_t)(row0 + 8) * 128 + col) = hv;
                    }
                }
            }
        }
        __syncthreads();   // protect A smem before next tile's staging
    }
}

// ---------------- kernel 3: aggregate  h1[i] = Yt[i] + mean_d Yb[nbr[i][d]] ----------------
__global__ void __launch_bounds__(256) agg1_kernel(
    const float* __restrict__ Yt, const __half* __restrict__ Yb,
    const int* __restrict__ nbr, float* __restrict__ h1, int N)
{
    int wid = threadIdx.x >> 5, lid = threadIdx.x & 31;
    int node = blockIdx.x * 8 + wid;
    if (node >= N) return;
    const int* nb = nbr + (size_t)node * DEG;
    float a0 = 0.f, a1 = 0.f, a2 = 0.f, a3 = 0.f;
    #pragma unroll
    for (int d = 0; d < DEG; d++) {
        int j = __ldg(nb + d);
        uint2 u = *(const uint2*)(Yb + (size_t)j * 128 + lid * 4);
        __half2 p0 = *reinterpret_cast<__half2*>(&u.x);
        __half2 p1 = *reinterpret_cast<__half2*>(&u.y);
        float2 f0 = __half22float2(p0);
        float2 f1 = __half22float2(p1);
        a0 += f0.x; a1 += f0.y; a2 += f1.x; a3 += f1.y;
    }
    float4 t = *(const float4*)(Yt + (size_t)node * 128 + lid * 4);
    float4 o;
    o.x = t.x + a0 * 0.0625f;
    o.y = t.y + a1 * 0.0625f;
    o.z = t.z + a2 * 0.0625f;
    o.w = t.w + a3 * 0.0625f;
    *(float4*)(h1 + (size_t)node * 128 + lid * 4) = o;
}

// ---------------- kernel 4: fused layer-2 (FFMA2 register-tiled) ----------------
#define XPITCH 260
typedef unsigned long long u64;
__device__ __forceinline__ u64 pk2(float lo, float hi) {
    u64 r; asm("mov.b64 %0, {%1, %2};" : "=l"(r) : "f"(lo), "f"(hi)); return r;
}
__device__ __forceinline__ void upk2(u64 v, float& lo, float& hi) {
    asm("mov.b64 {%0, %1}, %2;" : "=f"(lo), "=f"(hi) : "l"(v));
}
__device__ __forceinline__ u64 ffma2(u64 a, u64 b, u64 c) {
    u64 d; asm("fma.rn.f32x2 %0, %1, %2, %3;" : "=l"(d) : "l"(a), "l"(b), "l"(c)); return d;
}

template<int TILE>
__global__ void __launch_bounds__(256, 1) layer2_kernel(
    const float* __restrict__ src,          // h1 [N,128]
    const float* __restrict__ w,            // w2 [256,128]
    const int*   __restrict__ nbr,
    const int*   __restrict__ nodes,
    float*       __restrict__ out,
    int nRows)
{
    constexpr int RPT = TILE / 8;
    extern __shared__ float smemf[];
    float* x_s = smemf;                       // [TILE][XPITCH]
    float* w_s = smemf + TILE * XPITCH;       // [256][128]
    __shared__ int nb_s[TILE * DEG];
    __shared__ int self_s[TILE];

    const int tid  = threadIdx.x;
    const int base = blockIdx.x * TILE;

    {
        const float4* w4  = (const float4*)w;
        float4*       ws4 = (float4*)w_s;
        #pragma unroll 4
        for (int i = tid; i < (KDIM * H) / 4; i += 256) ws4[i] = w4[i];
    }
    for (int i = tid; i < TILE; i += 256) {
        int r = base + i;
        self_s[i] = (r < nRows) ? nodes[r] : 0;
    }
    __syncthreads();
    for (int i = tid; i < TILE * DEG; i += 256) {
        int node = i >> 4, d = i & 15;
        nb_s[i] = nbr[(size_t)self_s[node] * DEG + d];
    }
    __syncthreads();

    for (int i = tid; i < TILE * (F / 4); i += 256) {
        int node = i >> 5;
        int k0   = (i & 31) * 4;
        const float4 sv = *(const float4*)(src + (size_t)self_s[node] * F + k0);
        *(float4*)&x_s[node * XPITCH + k0] = sv;
        float ax = 0.f, ay = 0.f, az = 0.f, aw = 0.f;
        const int* nb = &nb_s[node * DEG];
        #pragma unroll
        for (int d = 0; d < DEG; d++) {
            const float4 v = *(const float4*)(src + (size_t)nb[d] * F + k0);
            ax += v.x; ay += v.y; az += v.z; aw += v.w;
        }
        float4 av;
        av.x = ax * 0.0625f; av.y = ay * 0.0625f;
        av.z = az * 0.0625f; av.w = aw * 0.0625f;
        *(float4*)&x_s[node * XPITCH + F + k0] = av;
    }
    __syncthreads();

    const int tx   = tid & 31;
    const int ty   = tid >> 5;
    const int col  = tx * 4;
    const int row0 = ty * RPT;

    u64 acc[RPT][2];
    #pragma unroll
    for (int n = 0; n < RPT; n++) { acc[n][0] = 0ULL; acc[n][1] = 0ULL; }

    const float* xb = &x_s[row0 * XPITCH];

    for (int k0 = 0; k0 < KDIM; k0 += 4) {
        u64 wb[4][2];
        #pragma unroll
        for (int ki = 0; ki < 4; ki++) {
            const float4 wv = *(const float4*)&w_s[(k0 + ki) * H + col];
            wb[ki][0] = pk2(wv.x, wv.y);
            wb[ki][1] = pk2(wv.z, wv.w);
        }
        #pragma unroll
        for (int n = 0; n < RPT; n++) {
            const float4 xv = *(const float4*)&xb[n * XPITCH + k0];
            u64 xa;
            xa = pk2(xv.x, xv.x);
            acc[n][0] = ffma2(xa, wb[0][0], acc[n][0]);
            acc[n][1] = ffma2(xa, wb[0][1], acc[n][1]);
            xa = pk2(xv.y, xv.y);
            acc[n][0] = ffma2(xa, wb[1][0], acc[n][0]);
            acc[n][1] = ffma2(xa, wb[1][1], acc[n][1]);
            xa = pk2(xv.z, xv.z);
            acc[n][0] = ffma2(xa, wb[2][0], acc[n][0]);
            acc[n][1] = ffma2(xa, wb[2][1], acc[n][1]);
            xa = pk2(xv.w, xv.w);
            acc[n][0] = ffma2(xa, wb[3][0], acc[n][0]);
            acc[n][1] = ffma2(xa, wb[3][1], acc[n][1]);
        }
    }

    #pragma unroll
    for (int n = 0; n < RPT; n++) {
        int r = base + row0 + n;
        if (r < nRows) {
            float4 o;
            upk2(acc[n][0], o.x, o.y);
            upk2(acc[n][1], o.z, o.w);
            *(float4*)&out[(size_t)r * H + col] = o;
        }
    }
}

// ---------------- host ----------------
extern "C" void kernel_launch(void* const* d_in, const int* in_sizes, int n_in,
                              void* d_out, int out_size)
{
    const float* features     = (const float*)d_in[0];
    const float* w1           = (const float*)d_in[1];
    const float* w2           = (const float*)d_in[2];
    const int*   neighbor_idx = (const int*)d_in[3];
    const int*   nodes        = (const int*)d_in[4];
    float*       out          = (float*)d_out;

    const int N = in_sizes[0] / F;
    const int B = in_sizes[4];

    float* Yt;  float* h1p;  __half* Yb;
    cudaGetSymbolAddress((void**)&Yt,  g_Yt);
    cudaGetSymbolAddress((void**)&Yb,  g_Yb);
    cudaGetSymbolAddress((void**)&h1p, g_h1);

    // 1) weight transpose + bf16 hi/lo split (padded B images)
    prep_w_kernel<<<128, 256>>>(w1);

    // 2) persistent mma.sync GEMM: Yt / Yb for all N
    const int nTiles = (N + 127) / 128;
    cudaFuncSetAttribute(gemm1_kernel, cudaFuncAttributeMaxDynamicSharedMemorySize, SMEM_GEMM);
    gemm1_kernel<<<dim3(148, 2), 256, SMEM_GEMM>>>(features, Yt, Yb, N, nTiles);

    // 3) gather-mean aggregate -> h1
    agg1_kernel<<<(N + 7) / 8, 256>>>(Yt, Yb, neighbor_idx, h1p, N);

    // 4) fused layer 2
    const int smem2 = (32 * XPITCH + KDIM * H) * (int)sizeof(float);
    cudaFuncSetAttribute(layer2_kernel<32>, cudaFuncAttributeMaxDynamicSharedMemorySize, smem2);
    layer2_kernel<32><<<(B + 31) / 32, 256, smem2>>>(h1p, w2, neighbor_idx, nodes, out, B);
}

// round 4
// speedup vs baseline: 1.7068x; 1.3415x over previous
#include <cuda_runtime.h>
#include <cuda_bf16.h>
#include <cuda_fp16.h>
#include <cstdint>

#define F      128
#define H      128
#define DEG    16
#define KDIM   256
#define NMAX   131072
#define PITCH  136            // bf16 elems per smem row; 272B row ≡ 4 words (mod 32) -> conflict-free
#define ROWB   (PITCH * 2)    // 272 bytes per row
#define SLAB   (128 * ROWB)   // 34816 B per [128r x 128k] bf16 slab

// ---------------- scratch (static __device__: allocation-free) ----------------
__device__ float         g_Yt[(size_t)NMAX * 128];     // f @ w1_top  (fp32)
__device__ __half        g_Yb[(size_t)NMAX * 128];     // f @ w1_bot  (fp16, gathered)
__device__ float         g_h1[(size_t)NMAX * 128];     // layer-1 embeddings
__device__ __nv_bfloat16 g_Bimg[2][2][128 * PITCH];    // [ch][lvl] pre-split B tiles [n][k]

// ---------------- PTX helpers ----------------
__device__ __forceinline__ void mma16816(float* c, const uint32_t* a, const uint32_t* b) {
    asm volatile(
        "mma.sync.aligned.m16n8k16.row.col.f32.bf16.bf16.f32 "
        "{%0,%1,%2,%3}, {%4,%5,%6,%7}, {%8,%9}, {%0,%1,%2,%3};"
        : "+f"(c[0]), "+f"(c[1]), "+f"(c[2]), "+f"(c[3])
        : "r"(a[0]), "r"(a[1]), "r"(a[2]), "r"(a[3]), "r"(b[0]), "r"(b[1]));
}
__device__ __forceinline__ void ldsm4(uint32_t* r, uint32_t addr) {
    asm volatile("ldmatrix.sync.aligned.m8n8.x4.shared.b16 {%0,%1,%2,%3}, [%4];"
        : "=r"(r[0]), "=r"(r[1]), "=r"(r[2]), "=r"(r[3]) : "r"(addr));
}
__device__ __forceinline__ uint32_t smem_u32(const void* p) {
    return (uint32_t)__cvta_generic_to_shared(p);
}
__device__ __forceinline__ void split_bf16(float v, uint32_t& hi, uint32_t& lo) {
    __nv_bfloat16 h = __float2bfloat16_rn(v);
    __nv_bfloat16 l = __float2bfloat16_rn(v - __bfloat162float(h));
    hi = __bfloat16_as_ushort(h);
    lo = __bfloat16_as_ushort(l);
}

// ---------------- kernel 1: build bf16 hi/lo B images  B[ch][n][k] = w1[ch*128+k][n] ----------------
__global__ void prep_w_kernel(const float* __restrict__ w1) {
    int i = blockIdx.x * 256 + threadIdx.x;          // 2*128*128 = 32768
    if (i >= 2 * 128 * 128) return;
    int ch = i >> 14;
    int n  = (i >> 7) & 127;
    int k  = i & 127;
    float v = w1[(size_t)(ch * 128 + k) * 128 + n];
    uint32_t hb, lb;
    split_bf16(v, hb, lb);
    g_Bimg[ch][0][n * PITCH + k] = __ushort_as_bfloat16((unsigned short)hb);
    g_Bimg[ch][1][n * PITCH + k] = __ushort_as_bfloat16((unsigned short)lb);
}

// ---------------- kernel 2: persistent bf16x3 mma.sync GEMM, double-buffered, ldmatrix ----------------
// smem layout (bytes): A[buf2][lvl2] slabs @ (buf*2+lvl)*SLAB; B[lvl2] @ 4*SLAB + lvl*SLAB
#define SMEM_GEMM (6 * SLAB)     // 208896 B

__global__ void __launch_bounds__(256, 1) gemm1_kernel(
    const float* __restrict__ f, float* __restrict__ Yt, __half* __restrict__ Yb,
    int nRows, int nTiles)
{
    extern __shared__ unsigned char smem[];
    const int tid = threadIdx.x, wid = tid >> 5, lid = tid & 31;
    const int ch  = blockIdx.y;
    const int g   = lid >> 2, tig = lid & 3;
    const int warp_m = wid & 3, warp_n = wid >> 2;
    const uint32_t smem_base = smem_u32(smem);

    // per-lane ldmatrix byte offsets
    const int offA = ((lid & 7) + ((lid >> 3) & 1) * 8) * ROWB + (lid >> 4) * 16;
    const int offB = ((lid & 7) + (lid >> 4) * 8) * ROWB + ((lid >> 3) & 1) * 16;

    // stage B once (linear copy of pre-built image: hi then lo, contiguous)
    {
        const uint4* src = (const uint4*)&g_Bimg[ch][0][0];
        uint4* dst = (uint4*)(smem + 4 * SLAB);
        #pragma unroll 4
        for (int i = tid; i < 2 * SLAB / 16; i += 256) dst[i] = src[i];
    }

    const int r_st  = tid >> 5;         // staging row within 8-row group
    const int k_st  = (tid & 31) * 4;   // staging k0 (elements)

    float4 Rst[16];

    // ---- load tile t's A rows into registers ----
    auto LOADT = [&](int t) {
        const int base = t * 128;
        #pragma unroll
        for (int j = 0; j < 16; j++) {
            int grow = base + j * 8 + r_st;
            if (grow < nRows)
                Rst[j] = *(const float4*)(f + (size_t)grow * 128 + k_st);
            else
                Rst[j] = make_float4(0.f, 0.f, 0.f, 0.f);
        }
    };
    // ---- convert + store registers into A buffer `buf` ----
    auto STORET = [&](int buf) {
        unsigned char* Ah = smem + (buf * 2 + 0) * SLAB;
        unsigned char* Al = smem + (buf * 2 + 1) * SLAB;
        #pragma unroll
        for (int j = 0; j < 16; j++) {
            uint32_t h0, h1v, h2, h3, l0, l1, l2, l3;
            split_bf16(Rst[j].x, h0, l0);
            split_bf16(Rst[j].y, h1v, l1);
            split_bf16(Rst[j].z, h2, l2);
            split_bf16(Rst[j].w, h3, l3);
            uint2 uh, ul;
            uh.x = (h1v << 16) | h0;  uh.y = (h3 << 16) | h2;
            ul.x = (l1  << 16) | l0;  ul.y = (l3 << 16) | l2;
            int r = j * 8 + r_st;
            *(uint2*)(Ah + r * ROWB + k_st * 2) = uh;
            *(uint2*)(Al + r * ROWB + k_st * 2) = ul;
        }
    };

    int cur = 0;
    int t = blockIdx.x;
    if (t < nTiles) { LOADT(t); STORET(0); }
    __syncthreads();

    while (t < nTiles) {
        const int tn   = t + gridDim.x;
        const int base = t * 128;

        // issue next tile's global loads (land under the MMA shadow)
        if (tn < nTiles) LOADT(tn);

        // ---- MMA: 3 products x 8 k-steps; warp tile 32x64, ldmatrix frags ----
        float acc[2][8][4];
        #pragma unroll
        for (int mb = 0; mb < 2; mb++)
            #pragma unroll
            for (int nb = 0; nb < 8; nb++)
                #pragma unroll
                for (int q = 0; q < 4; q++) acc[mb][nb][q] = 0.f;

        #pragma unroll
        for (int p = 0; p < 3; p++) {
            const uint32_t Abase = smem_base + (cur * 2 + (p == 1 ? 1 : 0)) * SLAB
                                 + warp_m * 32 * ROWB + offA;
            const uint32_t Bbase = smem_base + (4 + (p == 2 ? 1 : 0)) * SLAB
                                 + warp_n * 64 * ROWB + offB;
            #pragma unroll
            for (int ks = 0; ks < 8; ks++) {
                const int kB = ks * 32;            // k0*2 bytes
                uint32_t a[2][4];
                ldsm4(a[0], Abase + kB);
                ldsm4(a[1], Abase + 16 * ROWB + kB);
                uint32_t b[4][4];
                #pragma unroll
                for (int pr = 0; pr < 4; pr++)
                    ldsm4(b[pr], Bbase + pr * 16 * ROWB + kB);
                #pragma unroll
                for (int mb = 0; mb < 2; mb++)
                    #pragma unroll
                    for (int pr = 0; pr < 4; pr++) {
                        mma16816(acc[mb][pr * 2],     a[mb], &b[pr][0]);
                        mma16816(acc[mb][pr * 2 + 1], a[mb], &b[pr][2]);
                    }
            }
        }

        // ---- epilogue ----
        #pragma unroll
        for (int mb = 0; mb < 2; mb++) {
            int row0 = base + warp_m * 32 + mb * 16 + g;
            #pragma unroll
            for (int nb = 0; nb < 8; nb++) {
                int col = warp_n * 64 + nb * 8 + tig * 2;
                if (ch == 0) {
                    if (row0 < nRows)
                        *(float2*)(Yt + (size_t)row0 * 128 + col) =
                            make_float2(acc[mb][nb][0], acc[mb][nb][1]);
                    if (row0 + 8 < nRows)
                        *(float2*)(Yt + (size_t)(row0 + 8) * 128 + col) =
                            make_float2(acc[mb][nb][2], acc[mb][nb][3]);
                } else {
                    if (row0 < nRows)
                        *(__half2*)(Yb + (size_t)row0 * 128 + col) =
                            __floats2half2_rn(acc[mb][nb][0], acc[mb][nb][1]);
                    if (row0 + 8 < nRows)
                        *(__half2*)(Yb + (size_t)(row0 + 8) * 128 + col) =
                            __floats2half2_rn(acc[mb][nb][2], acc[mb][nb][3]);
                }
            }
        }

        // convert + store next tile into the other buffer, then flip
        if (tn < nTiles) STORET(cur ^ 1);
        __syncthreads();
        cur ^= 1;
        t = tn;
    }
}

// ---------------- kernel 3: aggregate  h1[i] = Yt[i] + mean_d Yb[nbr[i][d]] ----------------
__global__ void __launch_bounds__(256) agg1_kernel(
    const float* __restrict__ Yt, const __half* __restrict__ Yb,
    const int* __restrict__ nbr, float* __restrict__ h1, int N)
{
    int wid = threadIdx.x >> 5, lid = threadIdx.x & 31;
    int node = blockIdx.x * 8 + wid;
    if (node >= N) return;
    const int* nb = nbr + (size_t)node * DEG;
    float a0 = 0.f, a1 = 0.f, a2 = 0.f, a3 = 0.f;
    #pragma unroll
    for (int d = 0; d < DEG; d++) {
        int j = __ldg(nb + d);
        uint2 u = *(const uint2*)(Yb + (size_t)j * 128 + lid * 4);
        __half2 p0 = *reinterpret_cast<__half2*>(&u.x);
        __half2 p1 = *reinterpret_cast<__half2*>(&u.y);
        float2 f0 = __half22float2(p0);
        float2 f1 = __half22float2(p1);
        a0 += f0.x; a1 += f0.y; a2 += f1.x; a3 += f1.y;
    }
    float4 t = *(const float4*)(Yt + (size_t)node * 128 + lid * 4);
    float4 o;
    o.x = t.x + a0 * 0.0625f;
    o.y = t.y + a1 * 0.0625f;
    o.z = t.z + a2 * 0.0625f;
    o.w = t.w + a3 * 0.0625f;
    *(float4*)(h1 + (size_t)node * 128 + lid * 4) = o;
}

// ---------------- kernel 4: fused layer-2 (FFMA2 register-tiled) ----------------
#define XPITCH 260
typedef unsigned long long u64;
__device__ __forceinline__ u64 pk2(float lo, float hi) {
    u64 r; asm("mov.b64 %0, {%1, %2};" : "=l"(r) : "f"(lo), "f"(hi)); return r;
}
__device__ __forceinline__ void upk2(u64 v, float& lo, float& hi) {
    asm("mov.b64 {%0, %1}, %2;" : "=f"(lo), "=f"(hi) : "l"(v));
}
__device__ __forceinline__ u64 ffma2(u64 a, u64 b, u64 c) {
    u64 d; asm("fma.rn.f32x2 %0, %1, %2, %3;" : "=l"(d) : "l"(a), "l"(b), "l"(c)); return d;
}

template<int TILE>
__global__ void __launch_bounds__(256, 1) layer2_kernel(
    const float* __restrict__ src,          // h1 [N,128]
    const float* __restrict__ w,            // w2 [256,128]
    const int*   __restrict__ nbr,
    const int*   __restrict__ nodes,
    float*       __restrict__ out,
    int nRows)
{
    constexpr int RPT = TILE / 8;
    extern __shared__ float smemf[];
    float* x_s = smemf;                       // [TILE][XPITCH]
    float* w_s = smemf + TILE * XPITCH;       // [256][128]
    __shared__ int nb_s[TILE * DEG];
    __shared__ int self_s[TILE];

    const int tid  = threadIdx.x;
    const int base = blockIdx.x * TILE;

    {
        const float4* w4  = (const float4*)w;
        float4*       ws4 = (float4*)w_s;
        #pragma unroll 4
        for (int i = tid; i < (KDIM * H) / 4; i += 256) ws4[i] = w4[i];
    }
    for (int i = tid; i < TILE; i += 256) {
        int r = base + i;
        self_s[i] = (r < nRows) ? nodes[r] : 0;
    }
    __syncthreads();
    for (int i = tid; i < TILE * DEG; i += 256) {
        int node = i >> 4, d = i & 15;
        nb_s[i] = nbr[(size_t)self_s[node] * DEG + d];
    }
    __syncthreads();

    for (int i = tid; i < TILE * (F / 4); i += 256) {
        int node = i >> 5;
        int k0   = (i & 31) * 4;
        const float4 sv = *(const float4*)(src + (size_t)self_s[node] * F + k0);
        *(float4*)&x_s[node * XPITCH + k0] = sv;
        float ax = 0.f, ay = 0.f, az = 0.f, aw = 0.f;
        const int* nb = &nb_s[node * DEG];
        #pragma unroll
        for (int d = 0; d < DEG; d++) {
            const float4 v = *(const float4*)(src + (size_t)nb[d] * F + k0);
            ax += v.x; ay += v.y; az += v.z; aw += v.w;
        }
        float4 av;
        av.x = ax * 0.0625f; av.y = ay * 0.0625f;
        av.z = az * 0.0625f; av.w = aw * 0.0625f;
        *(float4*)&x_s[node * XPITCH + F + k0] = av;
    }
    __syncthreads();

    const int tx   = tid & 31;
    const int ty   = tid >> 5;
    const int col  = tx * 4;
    const int row0 = ty * RPT;

    u64 acc[RPT][2];
    #pragma unroll
    for (int n = 0; n < RPT; n++) { acc[n][0] = 0ULL; acc[n][1] = 0ULL; }

    const float* xb = &x_s[row0 * XPITCH];

    for (int k0 = 0; k0 < KDIM; k0 += 4) {
        u64 wb[4][2];
        #pragma unroll
        for (int ki = 0; ki < 4; ki++) {
            const float4 wv = *(const float4*)&w_s[(k0 + ki) * H + col];
            wb[ki][0] = pk2(wv.x, wv.y);
            wb[ki][1] = pk2(wv.z, wv.w);
        }
        #pragma unroll
        for (int n = 0; n < RPT; n++) {
            const float4 xv = *(const float4*)&xb[n * XPITCH + k0];
            u64 xa;
            xa = pk2(xv.x, xv.x);
            acc[n][0] = ffma2(xa, wb[0][0], acc[n][0]);
            acc[n][1] = ffma2(xa, wb[0][1], acc[n][1]);
            xa = pk2(xv.y, xv.y);
            acc[n][0] = ffma2(xa, wb[1][0], acc[n][0]);
            acc[n][1] = ffma2(xa, wb[1][1], acc[n][1]);
            xa = pk2(xv.z, xv.z);
            acc[n][0] = ffma2(xa, wb[2][0], acc[n][0]);
            acc[n][1] = ffma2(xa, wb[2][1], acc[n][1]);
            xa = pk2(xv.w, xv.w);
            acc[n][0] = ffma2(xa, wb[3][0], acc[n][0]);
            acc[n][1] = ffma2(xa, wb[3][1], acc[n][1]);
        }
    }

    #pragma unroll
    for (int n = 0; n < RPT; n++) {
        int r = base + row0 + n;
        if (r < nRows) {
            float4 o;
            upk2(acc[n][0], o.x, o.y);
            upk2(acc[n][1], o.z, o.w);
            *(float4*)&out[(size_t)r * H + col] = o;
        }
    }
}

// ---------------- host ----------------
extern "C" void kernel_launch(void* const* d_in, const int* in_sizes, int n_in,
                              void* d_out, int out_size)
{
    const float* features     = (const float*)d_in[0];
    const float* w1           = (const float*)d_in[1];
    const float* w2           = (const float*)d_in[2];
    const int*   neighbor_idx = (const int*)d_in[3];
    const int*   nodes        = (const int*)d_in[4];
    float*       out          = (float*)d_out;

    const int N = in_sizes[0] / F;
    const int B = in_sizes[4];

    float* Yt;  float* h1p;  __half* Yb;
    cudaGetSymbolAddress((void**)&Yt,  g_Yt);
    cudaGetSymbolAddress((void**)&Yb,  g_Yb);
    cudaGetSymbolAddress((void**)&h1p, g_h1);

    // 1) weight transpose + bf16 hi/lo split
    prep_w_kernel<<<128, 256>>>(w1);

    // 2) persistent mma.sync GEMM: Yt / Yb for all N
    const int nTiles = (N + 127) / 128;
    cudaFuncSetAttribute(gemm1_kernel, cudaFuncAttributeMaxDynamicSharedMemorySize, SMEM_GEMM);
    gemm1_kernel<<<dim3(148, 2), 256, SMEM_GEMM>>>(features, Yt, Yb, N, nTiles);

    // 3) gather-mean aggregate -> h1
    agg1_kernel<<<(N + 7) / 8, 256>>>(Yt, Yb, neighbor_idx, h1p, N);

    // 4) fused layer 2
    const int smem2 = (32 * XPITCH + KDIM * H) * (int)sizeof(float);
    cudaFuncSetAttribute(layer2_kernel<32>, cudaFuncAttributeMaxDynamicSharedMemorySize, smem2);
    layer2_kernel<32><<<(B + 31) / 32, 256, smem2>>>(h1p, w2, neighbor_idx, nodes, out, B);
}

// round 5
// speedup vs baseline: 2.0221x; 1.1847x over previous
#include <cuda_runtime.h>
#include <cuda_bf16.h>
#include <cuda_fp16.h>
#include <cstdint>

#define F      128
#define H      128
#define DEG    16
#define KDIM   256
#define NMAX   131072
#define BMAX   16384
#define PITCH  136            // bf16/row gemm1; 272 B ≡ 4 words (mod 32) -> conflict-free
#define ROWB   272
#define HSLAB  (64 * ROWB)    // 17408 B  (64-row A half-slab)
#define SLAB   (128 * ROWB)   // 34816 B  (128-n B slab)
#define ABUF_T (4 * HSLAB)    // 69632 B  (A: 2 buf x 2 lvl)
#define SMEM_G1 (ABUF_T + 4 * SLAB)   // 208896 B

#define PITCH2 264            // bf16/row gemm2 (K=256); 528 B ≡ 4 words (mod 32)
#define ROWB2  528
#define A2SLAB (64 * ROWB2)   // 33792 B per lvl
#define B2SLAB (128 * ROWB2)  // 67584 B per lvl
#define SMEM_G2 (2 * A2SLAB + 2 * B2SLAB)  // 202752 B

// ---------------- scratch ----------------
__device__ float         g_Yt[(size_t)NMAX * 128];
__device__ __half        g_Yb[(size_t)NMAX * 128];
__device__ float         g_h1[(size_t)NMAX * 128];
__device__ __nv_bfloat16 g_Bimg[2][2][128 * PITCH];     // [ch][lvl][n][k]  (w1)
__device__ __nv_bfloat16 g_B2img[2][128 * PITCH2];      // [lvl][n][k]      (w2)
__device__ __nv_bfloat16 g_x2h[(size_t)BMAX * 256];     // layer2 input hi
__device__ __nv_bfloat16 g_x2l[(size_t)BMAX * 256];     // layer2 input lo

// ---------------- PTX helpers ----------------
__device__ __forceinline__ void mma16816(float* c, const uint32_t* a, const uint32_t* b) {
    asm volatile(
        "mma.sync.aligned.m16n8k16.row.col.f32.bf16.bf16.f32 "
        "{%0,%1,%2,%3}, {%4,%5,%6,%7}, {%8,%9}, {%0,%1,%2,%3};"
        : "+f"(c[0]), "+f"(c[1]), "+f"(c[2]), "+f"(c[3])
        : "r"(a[0]), "r"(a[1]), "r"(a[2]), "r"(a[3]), "r"(b[0]), "r"(b[1]));
}
__device__ __forceinline__ void ldsm4(uint32_t* r, uint32_t addr) {
    asm volatile("ldmatrix.sync.aligned.m8n8.x4.shared.b16 {%0,%1,%2,%3}, [%4];"
        : "=r"(r[0]), "=r"(r[1]), "=r"(r[2]), "=r"(r[3]) : "r"(addr));
}
__device__ __forceinline__ uint32_t smem_u32(const void* p) {
    return (uint32_t)__cvta_generic_to_shared(p);
}
__device__ __forceinline__ void split_bf16(float v, uint32_t& hi, uint32_t& lo) {
    __nv_bfloat16 h = __float2bfloat16_rn(v);
    __nv_bfloat16 l = __float2bfloat16_rn(v - __bfloat162float(h));
    hi = __bfloat16_as_ushort(h);
    lo = __bfloat16_as_ushort(l);
}

// ---------------- kernel 1: build hi/lo weight images ----------------
// w1: Bimg[ch][lvl][n][k] = split(w1[ch*128+k][n]);  w2: B2img[lvl][n][k] = split(w2[k][n])
__global__ void prep_kernel(const float* __restrict__ w1, const float* __restrict__ w2) {
    int i = blockIdx.x * 256 + threadIdx.x;          // 65536 total
    if (i < 32768) {
        int ch = i >> 14, n = (i >> 7) & 127, k = i & 127;
        float v = w1[(size_t)(ch * 128 + k) * 128 + n];
        uint32_t hb, lb;
        split_bf16(v, hb, lb);
        g_Bimg[ch][0][n * PITCH + k] = __ushort_as_bfloat16((unsigned short)hb);
        g_Bimg[ch][1][n * PITCH + k] = __ushort_as_bfloat16((unsigned short)lb);
    } else if (i < 65536) {
        int j = i - 32768;
        int n = j & 127, k = j >> 7;                 // k in 0..255
        float v = w2[(size_t)k * 128 + n];
        uint32_t hb, lb;
        split_bf16(v, hb, lb);
        g_B2img[0][n * PITCH2 + k] = __ushort_as_bfloat16((unsigned short)hb);
        g_B2img[1][n * PITCH2 + k] = __ushort_as_bfloat16((unsigned short)lb);
    }
}

// ---------------- kernel 2: gemm1  Y[N,256] = f[N,128] @ w1', bf16x3, both halves ----------------
// smem: A[buf2][lvl2] @ (buf*2+lvl)*HSLAB ; B[ch2][lvl2] @ ABUF_T + (ch*2+lvl)*SLAB
__global__ void __launch_bounds__(256, 1) gemm1_kernel(
    const float* __restrict__ f, float* __restrict__ Yt, __half* __restrict__ Yb,
    int nRows, int nHT)
{
    extern __shared__ unsigned char smem[];
    const int tid = threadIdx.x, wid = tid >> 5, lid = tid & 31;
    const int g   = lid >> 2, tig = lid & 3;
    const int warp_m = wid & 1, warp_n = wid >> 1;       // 2 x 32 rows, 4 x 64 cols
    const int chn = warp_n >> 1, ncl = (warp_n & 1) * 64;
    const uint32_t smem_base = smem_u32(smem);

    const int offA = ((lid & 7) + ((lid >> 3) & 1) * 8) * ROWB + (lid >> 4) * 16;
    const int offB = ((lid & 7) + (lid >> 4) * 8) * ROWB + ((lid >> 3) & 1) * 16;

    // stage all 4 B slabs (g_Bimg is contiguous [ch][lvl])
    {
        const uint4* src = (const uint4*)&g_Bimg[0][0][0];
        uint4* dst = (uint4*)(smem + ABUF_T);
        #pragma unroll 4
        for (int i = tid; i < 4 * SLAB / 16; i += 256) dst[i] = src[i];
    }

    const int r_st = tid >> 5;          // row in 8-row group
    const int k_st = (tid & 31) * 4;    // k0 elements

    float4 Rst[8];
    auto LOADHT = [&](int ht) {
        const int base = ht * 64;
        #pragma unroll
        for (int j = 0; j < 8; j++) {
            int grow = base + j * 8 + r_st;
            Rst[j] = (grow < nRows) ? *(const float4*)(f + (size_t)grow * 128 + k_st)
                                    : make_float4(0.f, 0.f, 0.f, 0.f);
        }
    };
    auto STOREHT = [&](int buf) {
        unsigned char* Ah = smem + (buf * 2 + 0) * HSLAB;
        unsigned char* Al = smem + (buf * 2 + 1) * HSLAB;
        #pragma unroll
        for (int j = 0; j < 8; j++) {
            uint32_t h0, h1v, h2, h3, l0, l1, l2, l3;
            split_bf16(Rst[j].x, h0, l0);
            split_bf16(Rst[j].y, h1v, l1);
            split_bf16(Rst[j].z, h2, l2);
            split_bf16(Rst[j].w, h3, l3);
            uint2 uh, ul;
            uh.x = (h1v << 16) | h0;  uh.y = (h3 << 16) | h2;
            ul.x = (l1  << 16) | l0;  ul.y = (l3 << 16) | l2;
            int r = j * 8 + r_st;
            *(uint2*)(Ah + r * ROWB + k_st * 2) = uh;
            *(uint2*)(Al + r * ROWB + k_st * 2) = ul;
        }
    };

    int cur = 0;
    int ht = blockIdx.x;
    if (ht < nHT) { LOADHT(ht); STOREHT(0); }
    __syncthreads();

    while (ht < nHT) {
        const int htn  = ht + gridDim.x;
        const int base = ht * 64;

        if (htn < nHT) LOADHT(htn);

        float acc[2][8][4];
        #pragma unroll
        for (int mb = 0; mb < 2; mb++)
            #pragma unroll
            for (int nb = 0; nb < 8; nb++)
                #pragma unroll
                for (int q = 0; q < 4; q++) acc[mb][nb][q] = 0.f;

        #pragma unroll
        for (int p = 0; p < 3; p++) {
            const uint32_t Abase = smem_base + (cur * 2 + (p == 1 ? 1 : 0)) * HSLAB
                                 + warp_m * 32 * ROWB + offA;
            const uint32_t Bbase = smem_base + ABUF_T + (chn * 2 + (p == 2 ? 1 : 0)) * SLAB
                                 + ncl * ROWB + offB;
            #pragma unroll
            for (int ks = 0; ks < 8; ks++) {
                const int kB = ks * 32;
                uint32_t a[2][4];
                ldsm4(a[0], Abase + kB);
                ldsm4(a[1], Abase + 16 * ROWB + kB);
                uint32_t b[4][4];
                #pragma unroll
                for (int pr = 0; pr < 4; pr++)
                    ldsm4(b[pr], Bbase + pr * 16 * ROWB + kB);
                #pragma unroll
                for (int mb = 0; mb < 2; mb++)
                    #pragma unroll
                    for (int pr = 0; pr < 4; pr++) {
                        mma16816(acc[mb][pr * 2],     a[mb], &b[pr][0]);
                        mma16816(acc[mb][pr * 2 + 1], a[mb], &b[pr][2]);
                    }
            }
        }

        // epilogue: warp_n 0,1 -> Yt cols 0..127 fp32; warp_n 2,3 -> Yb cols 0..127 fp16
        #pragma unroll
        for (int mb = 0; mb < 2; mb++) {
            int row0 = base + warp_m * 32 + mb * 16 + g;
            #pragma unroll
            for (int nb = 0; nb < 8; nb++) {
                int col = (warp_n & 1) * 64 + nb * 8 + tig * 2;
                if (chn == 0) {
                    if (row0 < nRows)
                        *(float2*)(Yt + (size_t)row0 * 128 + col) =
                            make_float2(acc[mb][nb][0], acc[mb][nb][1]);
                    if (row0 + 8 < nRows)
                        *(float2*)(Yt + (size_t)(row0 + 8) * 128 + col) =
                            make_float2(acc[mb][nb][2], acc[mb][nb][3]);
                } else {
                    if (row0 < nRows)
                        *(__half2*)(Yb + (size_t)row0 * 128 + col) =
                            __floats2half2_rn(acc[mb][nb][0], acc[mb][nb][1]);
                    if (row0 + 8 < nRows)
                        *(__half2*)(Yb + (size_t)(row0 + 8) * 128 + col) =
                            __floats2half2_rn(acc[mb][nb][2], acc[mb][nb][3]);
                }
            }
        }

        if (htn < nHT) STOREHT(cur ^ 1);
        __syncthreads();
        cur ^= 1;
        ht = htn;
    }
}

// ---------------- kernel 3: agg1  h1[i] = Yt[i] + mean_d Yb[nbr[i][d]] ----------------
__global__ void __launch_bounds__(256) agg1_kernel(
    const float* __restrict__ Yt, const __half* __restrict__ Yb,
    const int* __restrict__ nbr, float* __restrict__ h1, int N)
{
    int wid = threadIdx.x >> 5, lid = threadIdx.x & 31;
    int node = blockIdx.x * 8 + wid;
    if (node >= N) return;
    const int* nb = nbr + (size_t)node * DEG;
    float a0 = 0.f, a1 = 0.f, a2 = 0.f, a3 = 0.f;
    #pragma unroll
    for (int d = 0; d < DEG; d++) {
        int j = __ldg(nb + d);
        uint2 u = *(const uint2*)(Yb + (size_t)j * 128 + lid * 4);
        __half2 p0 = *reinterpret_cast<__half2*>(&u.x);
        __half2 p1 = *reinterpret_cast<__half2*>(&u.y);
        float2 f0 = __half22float2(p0);
        float2 f1 = __half22float2(p1);
        a0 += f0.x; a1 += f0.y; a2 += f1.x; a3 += f1.y;
    }
    float4 t = *(const float4*)(Yt + (size_t)node * 128 + lid * 4);
    float4 o;
    o.x = t.x + a0 * 0.0625f;
    o.y = t.y + a1 * 0.0625f;
    o.z = t.z + a2 * 0.0625f;
    o.w = t.w + a3 * 0.0625f;
    *(float4*)(h1 + (size_t)node * 128 + lid * 4) = o;
}

// ---------------- kernel 4: agg2  x2[b] = [h1[nodes[b]], mean(h1[nbr])], pre-split bf16 ----------------
__global__ void __launch_bounds__(256) agg2_kernel(
    const float* __restrict__ h1, const int* __restrict__ nbr,
    const int* __restrict__ nodes,
    __nv_bfloat16* __restrict__ x2h, __nv_bfloat16* __restrict__ x2l, int B)
{
    int wid = threadIdx.x >> 5, lid = threadIdx.x & 31;
    int b = blockIdx.x * 8 + wid;
    if (b >= B) return;
    int self = __ldg(nodes + b);

    float4 sv = *(const float4*)(h1 + (size_t)self * 128 + lid * 4);

    const int* nb = nbr + (size_t)self * DEG;
    float a0 = 0.f, a1 = 0.f, a2 = 0.f, a3 = 0.f;
    #pragma unroll
    for (int d = 0; d < DEG; d++) {
        int j = __ldg(nb + d);
        float4 v = *(const float4*)(h1 + (size_t)j * 128 + lid * 4);
        a0 += v.x; a1 += v.y; a2 += v.z; a3 += v.w;
    }
    a0 *= 0.0625f; a1 *= 0.0625f; a2 *= 0.0625f; a3 *= 0.0625f;

    uint32_t h[8], l[8];
    split_bf16(sv.x, h[0], l[0]);  split_bf16(sv.y, h[1], l[1]);
    split_bf16(sv.z, h[2], l[2]);  split_bf16(sv.w, h[3], l[3]);
    split_bf16(a0,   h[4], l[4]);  split_bf16(a1,   h[5], l[5]);
    split_bf16(a2,   h[6], l[6]);  split_bf16(a3,   h[7], l[7]);

    size_t base = (size_t)b * 256;
    *(uint2*)(x2h + base + lid * 4) =
        make_uint2((h[1] << 16) | h[0], (h[3] << 16) | h[2]);
    *(uint2*)(x2l + base + lid * 4) =
        make_uint2((l[1] << 16) | l[0], (l[3] << 16) | l[2]);
    *(uint2*)(x2h + base + 128 + lid * 4) =
        make_uint2((h[5] << 16) | h[4], (h[7] << 16) | h[6]);
    *(uint2*)(x2l + base + 128 + lid * 4) =
        make_uint2((l[5] << 16) | l[4], (l[7] << 16) | l[6]);
}

// ---------------- kernel 5: gemm2  out[B,128] = x2[B,256] @ w2, bf16x3 ----------------
// smem: A[lvl2] @ lvl*A2SLAB ; B[lvl2] @ 2*A2SLAB + lvl*B2SLAB
__global__ void __launch_bounds__(256, 1) gemm2_kernel(
    const __nv_bfloat16* __restrict__ x2h, const __nv_bfloat16* __restrict__ x2l,
    float* __restrict__ out, int B)
{
    extern __shared__ unsigned char smem[];
    const int tid = threadIdx.x, wid = tid >> 5, lid = tid & 31;
    const int g   = lid >> 2, tig = lid & 3;
    const int warp_m = wid & 1, warp_n = wid >> 1;   // 2 x 32 rows, 4 x 32 cols
    const uint32_t smem_base = smem_u32(smem);
    const int base = blockIdx.x * 64;

    const int offA = ((lid & 7) + ((lid >> 3) & 1) * 8) * ROWB2 + (lid >> 4) * 16;
    const int offB = ((lid & 7) + (lid >> 4) * 8) * ROWB2 + ((lid >> 3) & 1) * 16;

    // stage B (both levels, contiguous image)
    {
        const uint4* src = (const uint4*)&g_B2img[0][0];
        uint4* dst = (uint4*)(smem + 2 * A2SLAB);
        #pragma unroll 4
        for (int i = tid; i < 2 * B2SLAB / 16; i += 256) dst[i] = src[i];
    }
    // stage A: 64 rows x 512B per level, pitched to 528
    {
        int r = tid >> 2, q = tid & 3;               // r 0..63, 128B quarter
        int grow = base + r;
        const uint4* sh = (const uint4*)(x2h + (size_t)grow * 256) + q * 8;
        const uint4* sl = (const uint4*)(x2l + (size_t)grow * 256) + q * 8;
        uint4* dh = (uint4*)(smem + r * ROWB2 + q * 128);
        uint4* dl = (uint4*)(smem + A2SLAB + r * ROWB2 + q * 128);
        if (grow < B) {
            #pragma unroll
            for (int j = 0; j < 8; j++) { dh[j] = sh[j]; dl[j] = sl[j]; }
        } else {
            uint4 z = make_uint4(0, 0, 0, 0);
            #pragma unroll
            for (int j = 0; j < 8; j++) { dh[j] = z; dl[j] = z; }
        }
    }
    __syncthreads();

    float acc[2][4][4];
    #pragma unroll
    for (int mb = 0; mb < 2; mb++)
        #pragma unroll
        for (int nb = 0; nb < 4; nb++)
            #pragma unroll
            for (int q = 0; q < 4; q++) acc[mb][nb][q] = 0.f;

    #pragma unroll
    for (int p = 0; p < 3; p++) {
        const uint32_t Abase = smem_base + (p == 1 ? A2SLAB : 0)
                             + warp_m * 32 * ROWB2 + offA;
        const uint32_t Bbase = smem_base + 2 * A2SLAB + (p == 2 ? B2SLAB : 0)
                             + warp_n * 32 * ROWB2 + offB;
        #pragma unroll
        for (int ks = 0; ks < 16; ks++) {
            const int kB = ks * 32;
            uint32_t a[2][4];
            ldsm4(a[0], Abase + kB);
            ldsm4(a[1], Abase + 16 * ROWB2 + kB);
            uint32_t b[2][4];
            ldsm4(b[0], Bbase + kB);
            ldsm4(b[1], Bbase + 16 * ROWB2 + kB);
            #pragma unroll
            for (int mb = 0; mb < 2; mb++)
                #pragma unroll
                for (int pr = 0; pr < 2; pr++) {
                    mma16816(acc[mb][pr * 2],     a[mb], &b[pr][0]);
                    mma16816(acc[mb][pr * 2 + 1], a[mb], &b[pr][2]);
                }
        }
    }

    #pragma unroll
    for (int mb = 0; mb < 2; mb++) {
        int row0 = base + warp_m * 32 + mb * 16 + g;
        #pragma unroll
        for (int nb = 0; nb < 4; nb++) {
            int col = warp_n * 32 + nb * 8 + tig * 2;
            if (row0 < B)
                *(float2*)(out + (size_t)row0 * 128 + col) =
                    make_float2(acc[mb][nb][0], acc[mb][nb][1]);
            if (row0 + 8 < B)
                *(float2*)(out + (size_t)(row0 + 8) * 128 + col) =
                    make_float2(acc[mb][nb][2], acc[mb][nb][3]);
        }
    }
}

// ---------------- host ----------------
extern "C" void kernel_launch(void* const* d_in, const int* in_sizes, int n_in,
                              void* d_out, int out_size)
{
    const float* features     = (const float*)d_in[0];
    const float* w1           = (const float*)d_in[1];
    const float* w2           = (const float*)d_in[2];
    const int*   neighbor_idx = (const int*)d_in[3];
    const int*   nodes        = (const int*)d_in[4];
    float*       out          = (float*)d_out;

    const int N = in_sizes[0] / F;
    const int B = in_sizes[4];

    float* Yt;  float* h1p;  __half* Yb;  __nv_bfloat16 *x2h, *x2l;
    cudaGetSymbolAddress((void**)&Yt,  g_Yt);
    cudaGetSymbolAddress((void**)&Yb,  g_Yb);
    cudaGetSymbolAddress((void**)&h1p, g_h1);
    cudaGetSymbolAddress((void**)&x2h, g_x2h);
    cudaGetSymbolAddress((void**)&x2l, g_x2l);

    // 1) weight images (w1 + w2)
    prep_kernel<<<256, 256>>>(w1, w2);

    // 2) gemm1: Yt / Yb for all N (both col-halves, one wave)
    const int nHT = (N + 63) / 64;
    cudaFuncSetAttribute(gemm1_kernel, cudaFuncAttributeMaxDynamicSharedMemorySize, SMEM_G1);
    gemm1_kernel<<<148, 256, SMEM_G1>>>(features, Yt, Yb, N, nHT);

    // 3) agg1 -> h1
    agg1_kernel<<<(N + 7) / 8, 256>>>(Yt, Yb, neighbor_idx, h1p, N);

    // 4) agg2 -> x2 (pre-split bf16 hi/lo)
    agg2_kernel<<<(B + 7) / 8, 256>>>(h1p, neighbor_idx, nodes, x2h, x2l, B);

    // 5) gemm2 -> out
    cudaFuncSetAttribute(gemm2_kernel, cudaFuncAttributeMaxDynamicSharedMemorySize, SMEM_G2);
    gemm2_kernel<<<(B + 63) / 64, 256, SMEM_G2>>>(x2h, x2l, out, B);
}

// round 6
// speedup vs baseline: 2.6454x; 1.3083x over previous
#include <cuda_runtime.h>
#include <cuda_bf16.h>
#include <cuda_fp16.h>
#include <cstdint>

#define F      128
#define H      128
#define DEG    16
#define KDIM   256
#define NMAX   131072
#define BMAX   16384
#define PITCH  136            // fp16/row gemm1 (K=128); 272 B ≡ 4 words (mod 32) -> conflict-free
#define ROWB   272
#define HSLAB  (64 * ROWB)    // 17408 B  (64-row A half-slab, single fp16 level)
#define SLAB   (128 * ROWB)   // 34816 B  (128-n B slab)
#define ABUF_T (2 * HSLAB)    // 34816 B  (A: 2 buffers)
#define SMEM_G1 (ABUF_T + 4 * SLAB)   // 174080 B

#define PITCH2 264            // fp16/row gemm2 (K=256); 528 B ≡ 4 words (mod 32)
#define ROWB2  528
#define A2SLAB (64 * ROWB2)   // 33792 B (single level)
#define B2SLAB (128 * ROWB2)  // 67584 B per lvl
#define SMEM_G2 (A2SLAB + 2 * B2SLAB)  // 168960 B

// ---------------- scratch ----------------
__device__ float  g_Yt[(size_t)NMAX * 128];
__device__ __half g_Yb[(size_t)NMAX * 128];
__device__ float  g_h1[(size_t)NMAX * 128];
__device__ __half g_B1img[2][2][128 * PITCH];   // [ch][lvl][n][k]  (w1 hi/lo fp16)
__device__ __half g_B2img[2][128 * PITCH2];     // [lvl][n][k]      (w2 hi/lo fp16)
__device__ __half g_x2[(size_t)BMAX * 256];     // layer2 input (fp16, single)

// ---------------- PTX helpers ----------------
__device__ __forceinline__ void mma16816h(float* c, const uint32_t* a, const uint32_t* b) {
    asm volatile(
        "mma.sync.aligned.m16n8k16.row.col.f32.f16.f16.f32 "
        "{%0,%1,%2,%3}, {%4,%5,%6,%7}, {%8,%9}, {%0,%1,%2,%3};"
        : "+f"(c[0]), "+f"(c[1]), "+f"(c[2]), "+f"(c[3])
        : "r"(a[0]), "r"(a[1]), "r"(a[2]), "r"(a[3]), "r"(b[0]), "r"(b[1]));
}
__device__ __forceinline__ void ldsm4(uint32_t* r, uint32_t addr) {
    asm volatile("ldmatrix.sync.aligned.m8n8.x4.shared.b16 {%0,%1,%2,%3}, [%4];"
        : "=r"(r[0]), "=r"(r[1]), "=r"(r[2]), "=r"(r[3]) : "r"(addr));
}
__device__ __forceinline__ uint32_t smem_u32(const void* p) {
    return (uint32_t)__cvta_generic_to_shared(p);
}
__device__ __forceinline__ void split_fp16(float v, __half& hi, __half& lo) {
    hi = __float2half_rn(v);
    lo = __float2half_rn(v - __half2float(hi));
}
__device__ __forceinline__ uint32_t h2bits(__half2 h) {
    return *reinterpret_cast<uint32_t*>(&h);
}

// ---------------- kernel 1: build fp16 hi/lo weight images ----------------
// w1: B1img[ch][lvl][n][k] = split(w1[ch*128+k][n]);  w2: B2img[lvl][n][k] = split(w2[k][n])
__global__ void prep_kernel(const float* __restrict__ w1, const float* __restrict__ w2) {
    int i = blockIdx.x * 256 + threadIdx.x;          // 65536 total
    if (i < 32768) {
        int ch = i >> 14, n = (i >> 7) & 127, k = i & 127;
        float v = w1[(size_t)(ch * 128 + k) * 128 + n];
        __half hb, lb;
        split_fp16(v, hb, lb);
        g_B1img[ch][0][n * PITCH + k] = hb;
        g_B1img[ch][1][n * PITCH + k] = lb;
    } else if (i < 65536) {
        int j = i - 32768;
        int n = j & 127, k = j >> 7;                 // k in 0..255
        float v = w2[(size_t)k * 128 + n];
        __half hb, lb;
        split_fp16(v, hb, lb);
        g_B2img[0][n * PITCH2 + k] = hb;
        g_B2img[1][n * PITCH2 + k] = lb;
    }
}

// ---------------- kernel 2: gemm1  Y[N,256] = f16(f)[N,128] @ (w1h + w1l) ----------------
// smem: A[buf2] @ buf*HSLAB ; B[ch2][lvl2] @ ABUF_T + (ch*2+lvl)*SLAB
__global__ void __launch_bounds__(256, 1) gemm1_kernel(
    const float* __restrict__ f, float* __restrict__ Yt, __half* __restrict__ Yb,
    int nRows, int nHT)
{
    extern __shared__ unsigned char smem[];
    const int tid = threadIdx.x, wid = tid >> 5, lid = tid & 31;
    const int g   = lid >> 2, tig = lid & 3;
    const int warp_m = wid & 1, warp_n = wid >> 1;       // 2 x 32 rows, 4 x 64 cols
    const int chn = warp_n >> 1, ncl = (warp_n & 1) * 64;
    const uint32_t smem_base = smem_u32(smem);

    const int offA = ((lid & 7) + ((lid >> 3) & 1) * 8) * ROWB + (lid >> 4) * 16;
    const int offB = ((lid & 7) + (lid >> 4) * 8) * ROWB + ((lid >> 3) & 1) * 16;

    // stage all 4 B slabs (g_B1img is contiguous [ch][lvl])
    {
        const uint4* src = (const uint4*)&g_B1img[0][0][0];
        uint4* dst = (uint4*)(smem + ABUF_T);
        #pragma unroll 4
        for (int i = tid; i < 4 * SLAB / 16; i += 256) dst[i] = src[i];
    }

    const int r_st = tid >> 5;          // row in 8-row group
    const int k_st = (tid & 31) * 4;    // k0 elements

    float4 Rst[8];
    auto LOADHT = [&](int ht) {
        const int base = ht * 64;
        #pragma unroll
        for (int j = 0; j < 8; j++) {
            int grow = base + j * 8 + r_st;
            Rst[j] = (grow < nRows) ? *(const float4*)(f + (size_t)grow * 128 + k_st)
                                    : make_float4(0.f, 0.f, 0.f, 0.f);
        }
    };
    auto STOREHT = [&](int buf) {
        unsigned char* Ah = smem + buf * HSLAB;
        #pragma unroll
        for (int j = 0; j < 8; j++) {
            uint2 u;
            u.x = h2bits(__floats2half2_rn(Rst[j].x, Rst[j].y));
            u.y = h2bits(__floats2half2_rn(Rst[j].z, Rst[j].w));
            int r = j * 8 + r_st;
            *(uint2*)(Ah + r * ROWB + k_st * 2) = u;
        }
    };

    int cur = 0;
    int ht = blockIdx.x;
    if (ht < nHT) { LOADHT(ht); STOREHT(0); }
    __syncthreads();

    while (ht < nHT) {
        const int htn  = ht + gridDim.x;
        const int base = ht * 64;

        if (htn < nHT) LOADHT(htn);

        float acc[2][8][4];
        #pragma unroll
        for (int mb = 0; mb < 2; mb++)
            #pragma unroll
            for (int nb = 0; nb < 8; nb++)
                #pragma unroll
                for (int q = 0; q < 4; q++) acc[mb][nb][q] = 0.f;

        #pragma unroll
        for (int p = 0; p < 2; p++) {       // B level: hi, lo (A single fp16)
            const uint32_t Abase = smem_base + cur * HSLAB
                                 + warp_m * 32 * ROWB + offA;
            const uint32_t Bbase = smem_base + ABUF_T + (chn * 2 + p) * SLAB
                                 + ncl * ROWB + offB;
            #pragma unroll
            for (int ks = 0; ks < 8; ks++) {
                const int kB = ks * 32;
                uint32_t a[2][4];
                ldsm4(a[0], Abase + kB);
                ldsm4(a[1], Abase + 16 * ROWB + kB);
                uint32_t b[4][4];
                #pragma unroll
                for (int pr = 0; pr < 4; pr++)
                    ldsm4(b[pr], Bbase + pr * 16 * ROWB + kB);
                #pragma unroll
                for (int mb = 0; mb < 2; mb++)
                    #pragma unroll
                    for (int pr = 0; pr < 4; pr++) {
                        mma16816h(acc[mb][pr * 2],     a[mb], &b[pr][0]);
                        mma16816h(acc[mb][pr * 2 + 1], a[mb], &b[pr][2]);
                    }
            }
        }

        // epilogue: warp_n 0,1 -> Yt (fp32); warp_n 2,3 -> Yb (fp16)
        #pragma unroll
        for (int mb = 0; mb < 2; mb++) {
            int row0 = base + warp_m * 32 + mb * 16 + g;
            #pragma unroll
            for (int nb = 0; nb < 8; nb++) {
                int col = (warp_n & 1) * 64 + nb * 8 + tig * 2;
                if (chn == 0) {
                    if (row0 < nRows)
                        *(float2*)(Yt + (size_t)row0 * 128 + col) =
                            make_float2(acc[mb][nb][0], acc[mb][nb][1]);
                    if (row0 + 8 < nRows)
                        *(float2*)(Yt + (size_t)(row0 + 8) * 128 + col) =
                            make_float2(acc[mb][nb][2], acc[mb][nb][3]);
                } else {
                    if (row0 < nRows)
                        *(__half2*)(Yb + (size_t)row0 * 128 + col) =
                            __floats2half2_rn(acc[mb][nb][0], acc[mb][nb][1]);
                    if (row0 + 8 < nRows)
                        *(__half2*)(Yb + (size_t)(row0 + 8) * 128 + col) =
                            __floats2half2_rn(acc[mb][nb][2], acc[mb][nb][3]);
                }
            }
        }

        if (htn < nHT) STOREHT(cur ^ 1);
        __syncthreads();
        cur ^= 1;
        ht = htn;
    }
}

// ---------------- kernel 3: agg1  h1[i] = Yt[i] + mean_d Yb[nbr[i][d]] ----------------
__global__ void __launch_bounds__(256) agg1_kernel(
    const float* __restrict__ Yt, const __half* __restrict__ Yb,
    const int* __restrict__ nbr, float* __restrict__ h1, int N)
{
    int wid = threadIdx.x >> 5, lid = threadIdx.x & 31;
    int node = blockIdx.x * 8 + wid;
    if (node >= N) return;
    const int* nb = nbr + (size_t)node * DEG;
    float a0 = 0.f, a1 = 0.f, a2 = 0.f, a3 = 0.f;
    #pragma unroll
    for (int d = 0; d < DEG; d++) {
        int j = __ldg(nb + d);
        uint2 u = *(const uint2*)(Yb + (size_t)j * 128 + lid * 4);
        __half2 p0 = *reinterpret_cast<__half2*>(&u.x);
        __half2 p1 = *reinterpret_cast<__half2*>(&u.y);
        float2 f0 = __half22float2(p0);
        float2 f1 = __half22float2(p1);
        a0 += f0.x; a1 += f0.y; a2 += f1.x; a3 += f1.y;
    }
    float4 t = *(const float4*)(Yt + (size_t)node * 128 + lid * 4);
    float4 o;
    o.x = t.x + a0 * 0.0625f;
    o.y = t.y + a1 * 0.0625f;
    o.z = t.z + a2 * 0.0625f;
    o.w = t.w + a3 * 0.0625f;
    *(float4*)(h1 + (size_t)node * 128 + lid * 4) = o;
}

// ---------------- kernel 4: agg2  x2[b] = f16([h1[nodes[b]], mean(h1[nbr])]) ----------------
__global__ void __launch_bounds__(256) agg2_kernel(
    const float* __restrict__ h1, const int* __restrict__ nbr,
    const int* __restrict__ nodes, __half* __restrict__ x2, int B)
{
    int wid = threadIdx.x >> 5, lid = threadIdx.x & 31;
    int b = blockIdx.x * 8 + wid;
    if (b >= B) return;
    int self = __ldg(nodes + b);

    float4 sv = *(const float4*)(h1 + (size_t)self * 128 + lid * 4);

    const int* nb = nbr + (size_t)self * DEG;
    float a0 = 0.f, a1 = 0.f, a2 = 0.f, a3 = 0.f;
    #pragma unroll
    for (int d = 0; d < DEG; d++) {
        int j = __ldg(nb + d);
        float4 v = *(const float4*)(h1 + (size_t)j * 128 + lid * 4);
        a0 += v.x; a1 += v.y; a2 += v.z; a3 += v.w;
    }
    a0 *= 0.0625f; a1 *= 0.0625f; a2 *= 0.0625f; a3 *= 0.0625f;

    size_t base = (size_t)b * 256;
    *(uint2*)(x2 + base + lid * 4) =
        make_uint2(h2bits(__floats2half2_rn(sv.x, sv.y)),
                   h2bits(__floats2half2_rn(sv.z, sv.w)));
    *(uint2*)(x2 + base + 128 + lid * 4) =
        make_uint2(h2bits(__floats2half2_rn(a0, a1)),
                   h2bits(__floats2half2_rn(a2, a3)));
}

// ---------------- kernel 5: gemm2  out[B,128] = x2[B,256] @ (w2h + w2l) ----------------
// smem: A @ 0 (single fp16) ; B[lvl2] @ A2SLAB + lvl*B2SLAB
__global__ void __launch_bounds__(256, 1) gemm2_kernel(
    const __half* __restrict__ x2, float* __restrict__ out, int B)
{
    extern __shared__ unsigned char smem[];
    const int tid = threadIdx.x, wid = tid >> 5, lid = tid & 31;
    const int g   = lid >> 2, tig = lid & 3;
    const int warp_m = wid & 1, warp_n = wid >> 1;   // 2 x 32 rows, 4 x 32 cols
    const uint32_t smem_base = smem_u32(smem);
    const int base = blockIdx.x * 64;

    const int offA = ((lid & 7) + ((lid >> 3) & 1) * 8) * ROWB2 + (lid >> 4) * 16;
    const int offB = ((lid & 7) + (lid >> 4) * 8) * ROWB2 + ((lid >> 3) & 1) * 16;

    // stage B (both levels, contiguous image)
    {
        const uint4* src = (const uint4*)&g_B2img[0][0];
        uint4* dst = (uint4*)(smem + A2SLAB);
        #pragma unroll 4
        for (int i = tid; i < 2 * B2SLAB / 16; i += 256) dst[i] = src[i];
    }
    // stage A: 64 rows x 512B, pitched to 528
    {
        int r = tid >> 2, q = tid & 3;               // r 0..63, 128B quarter
        int grow = base + r;
        const uint4* sh = (const uint4*)(x2 + (size_t)grow * 256) + q * 8;
        uint4* dh = (uint4*)(smem + r * ROWB2 + q * 128);
        if (grow < B) {
            #pragma unroll
            for (int j = 0; j < 8; j++) dh[j] = sh[j];
        } else {
            uint4 z = make_uint4(0, 0, 0, 0);
            #pragma unroll
            for (int j = 0; j < 8; j++) dh[j] = z;
        }
    }
    __syncthreads();

    float acc[2][4][4];
    #pragma unroll
    for (int mb = 0; mb < 2; mb++)
        #pragma unroll
        for (int nb = 0; nb < 4; nb++)
            #pragma unroll
            for (int q = 0; q < 4; q++) acc[mb][nb][q] = 0.f;

    #pragma unroll
    for (int p = 0; p < 2; p++) {
        const uint32_t Abase = smem_base + warp_m * 32 * ROWB2 + offA;
        const uint32_t Bbase = smem_base + A2SLAB + p * B2SLAB
                             + warp_n * 32 * ROWB2 + offB;
        #pragma unroll
        for (int ks = 0; ks < 16; ks++) {
            const int kB = ks * 32;
            uint32_t a[2][4];
            ldsm4(a[0], Abase + kB);
            ldsm4(a[1], Abase + 16 * ROWB2 + kB);
            uint32_t b[2][4];
            ldsm4(b[0], Bbase + kB);
            ldsm4(b[1], Bbase + 16 * ROWB2 + kB);
            #pragma unroll
            for (int mb = 0; mb < 2; mb++)
                #pragma unroll
                for (int pr = 0; pr < 2; pr++) {
                    mma16816h(acc[mb][pr * 2],     a[mb], &b[pr][0]);
                    mma16816h(acc[mb][pr * 2 + 1], a[mb], &b[pr][2]);
                }
        }
    }

    #pragma unroll
    for (int mb = 0; mb < 2; mb++) {
        int row0 = base + warp_m * 32 + mb * 16 + g;
        #pragma unroll
        for (int nb = 0; nb < 4; nb++) {
            int col = warp_n * 32 + nb * 8 + tig * 2;
            if (row0 < B)
                *(float2*)(out + (size_t)row0 * 128 + col) =
                    make_float2(acc[mb][nb][0], acc[mb][nb][1]);
            if (row0 + 8 < B)
                *(float2*)(out + (size_t)(row0 + 8) * 128 + col) =
                    make_float2(acc[mb][nb][2], acc[mb][nb][3]);
        }
    }
}

// ---------------- host ----------------
extern "C" void kernel_launch(void* const* d_in, const int* in_sizes, int n_in,
                              void* d_out, int out_size)
{
    const float* features     = (const float*)d_in[0];
    const float* w1           = (const float*)d_in[1];
    const float* w2           = (const float*)d_in[2];
    const int*   neighbor_idx = (const int*)d_in[3];
    const int*   nodes        = (const int*)d_in[4];
    float*       out          = (float*)d_out;

    const int N = in_sizes[0] / F;
    const int B = in_sizes[4];

    float* Yt;  float* h1p;  __half* Yb;  __half* x2;
    cudaGetSymbolAddress((void**)&Yt,  g_Yt);
    cudaGetSymbolAddress((void**)&Yb,  g_Yb);
    cudaGetSymbolAddress((void**)&h1p, g_h1);
    cudaGetSymbolAddress((void**)&x2,  g_x2);

    // 1) weight images (w1 + w2, fp16 hi/lo)
    prep_kernel<<<256, 256>>>(w1, w2);

    // 2) gemm1: Yt / Yb for all N
    const int nHT = (N + 63) / 64;
    cudaFuncSetAttribute(gemm1_kernel, cudaFuncAttributeMaxDynamicSharedMemorySize, SMEM_G1);
    gemm1_kernel<<<148, 256, SMEM_G1>>>(features, Yt, Yb, N, nHT);

    // 3) agg1 -> h1
    agg1_kernel<<<(N + 7) / 8, 256>>>(Yt, Yb, neighbor_idx, h1p, N);

    // 4) agg2 -> x2 (fp16)
    agg2_kernel<<<(B + 7) / 8, 256>>>(h1p, neighbor_idx, nodes, x2, B);

    // 5) gemm2 -> out
    cudaFuncSetAttribute(gemm2_kernel, cudaFuncAttributeMaxDynamicSharedMemorySize, SMEM_G2);
    gemm2_kernel<<<(B + 63) / 64, 256, SMEM_G2>>>(x2, out, B);
}

// round 7
// speedup vs baseline: 2.9190x; 1.1034x over previous
#include <cuda_runtime.h>
#include <cuda_bf16.h>
#include <cuda_fp16.h>
#include <cstdint>

#define F      128
#define H      128
#define DEG    16
#define KDIM   256
#define NMAX   131072
#define BMAX   16384
#define PITCH  136            // fp16/row gemm1 (K=128); 272 B ≡ 4 words (mod 32) -> conflict-free
#define ROWB   272
#define HSLAB  (64 * ROWB)    // 17408 B  (64-row A half-slab)
#define SLAB   (128 * ROWB)   // 34816 B  (128-n B slab)
#define ABUF_T (2 * HSLAB)    // 34816 B  (A: 2 buffers)
#define SMEM_G1 (ABUF_T + 2 * SLAB)   // 104448 B -> 2 CTAs/SM

#define PITCH2 264            // fp16/row gemm2 (K=256); 528 B ≡ 4 words (mod 32)
#define ROWB2  528
#define A2SLAB (64 * ROWB2)   // 33792 B
#define B2SLAB (128 * ROWB2)  // 67584 B per lvl
#define SMEM_G2 (A2SLAB + 2 * B2SLAB)  // 168960 B

// ---------------- scratch ----------------
__device__ float  g_Yt[(size_t)NMAX * 128];
__device__ __half g_Yb[(size_t)NMAX * 128];
__device__ float  g_h1[(size_t)NMAX * 128];
__device__ __half g_B1img[2][128 * PITCH];      // [ch][n][k]   (w1 fp16, single level)
__device__ __half g_B2img[2][128 * PITCH2];     // [lvl][n][k]  (w2 hi/lo fp16)
__device__ __half g_x2[(size_t)BMAX * 256];     // layer2 input (fp16)

// ---------------- PTX helpers ----------------
__device__ __forceinline__ void mma16816h(float* c, const uint32_t* a, const uint32_t* b) {
    asm volatile(
        "mma.sync.aligned.m16n8k16.row.col.f32.f16.f16.f32 "
        "{%0,%1,%2,%3}, {%4,%5,%6,%7}, {%8,%9}, {%0,%1,%2,%3};"
        : "+f"(c[0]), "+f"(c[1]), "+f"(c[2]), "+f"(c[3])
        : "r"(a[0]), "r"(a[1]), "r"(a[2]), "r"(a[3]), "r"(b[0]), "r"(b[1]));
}
__device__ __forceinline__ void ldsm4(uint32_t* r, uint32_t addr) {
    asm volatile("ldmatrix.sync.aligned.m8n8.x4.shared.b16 {%0,%1,%2,%3}, [%4];"
        : "=r"(r[0]), "=r"(r[1]), "=r"(r[2]), "=r"(r[3]) : "r"(addr));
}
__device__ __forceinline__ uint32_t smem_u32(const void* p) {
    return (uint32_t)__cvta_generic_to_shared(p);
}
__device__ __forceinline__ void split_fp16(float v, __half& hi, __half& lo) {
    hi = __float2half_rn(v);
    lo = __float2half_rn(v - __half2float(hi));
}
__device__ __forceinline__ uint32_t h2bits(__half2 h) {
    return *reinterpret_cast<uint32_t*>(&h);
}

// ---------------- kernel 1: build fp16 weight images ----------------
// w1: B1img[ch][n][k] = f16(w1[ch*128+k][n]);  w2: B2img[lvl][n][k] = split(w2[k][n])
__global__ void prep_kernel(const float* __restrict__ w1, const float* __restrict__ w2) {
    int i = blockIdx.x * 256 + threadIdx.x;          // 65536 total
    if (i < 32768) {
        int ch = i >> 14, n = (i >> 7) & 127, k = i & 127;
        float v = w1[(size_t)(ch * 128 + k) * 128 + n];
        g_B1img[ch][n * PITCH + k] = __float2half_rn(v);
    } else if (i < 65536) {
        int j = i - 32768;
        int n = j & 127, k = j >> 7;                 // k in 0..255
        float v = w2[(size_t)k * 128 + n];
        __half hb, lb;
        split_fp16(v, hb, lb);
        g_B2img[0][n * PITCH2 + k] = hb;
        g_B2img[1][n * PITCH2 + k] = lb;
    }
}

// ---------------- kernel 2: gemm1  Y[N,256] = f16(f)[N,128] @ f16(w1) ----------------
// smem: A[buf2] @ buf*HSLAB ; B[ch2] @ ABUF_T + ch*SLAB
__global__ void __launch_bounds__(256, 2) gemm1_kernel(
    const float* __restrict__ f, float* __restrict__ Yt, __half* __restrict__ Yb,
    int nRows, int nHT)
{
    extern __shared__ unsigned char smem[];
    const int tid = threadIdx.x, wid = tid >> 5, lid = tid & 31;
    const int g   = lid >> 2, tig = lid & 3;
    const int warp_m = wid & 1, warp_n = wid >> 1;       // 2 x 32 rows, 4 x 64 cols
    const int chn = warp_n >> 1, ncl = (warp_n & 1) * 64;
    const uint32_t smem_base = smem_u32(smem);

    const int offA = ((lid & 7) + ((lid >> 3) & 1) * 8) * ROWB + (lid >> 4) * 16;
    const int offB = ((lid & 7) + (lid >> 4) * 8) * ROWB + ((lid >> 3) & 1) * 16;

    // stage both B slabs (g_B1img contiguous [ch])
    {
        const uint4* src = (const uint4*)&g_B1img[0][0];
        uint4* dst = (uint4*)(smem + ABUF_T);
        #pragma unroll 4
        for (int i = tid; i < 2 * SLAB / 16; i += 256) dst[i] = src[i];
    }

    const int r_st = tid >> 5;          // row in 8-row group
    const int k_st = (tid & 31) * 4;    // k0 elements

    float4 Rst[8];
    auto LOADHT = [&](int ht) {
        const int base = ht * 64;
        #pragma unroll
        for (int j = 0; j < 8; j++) {
            int grow = base + j * 8 + r_st;
            Rst[j] = (grow < nRows) ? *(const float4*)(f + (size_t)grow * 128 + k_st)
                                    : make_float4(0.f, 0.f, 0.f, 0.f);
        }
    };
    auto STOREHT = [&](int buf) {
        unsigned char* Ah = smem + buf * HSLAB;
        #pragma unroll
        for (int j = 0; j < 8; j++) {
            uint2 u;
            u.x = h2bits(__floats2half2_rn(Rst[j].x, Rst[j].y));
            u.y = h2bits(__floats2half2_rn(Rst[j].z, Rst[j].w));
            int r = j * 8 + r_st;
            *(uint2*)(Ah + r * ROWB + k_st * 2) = u;
        }
    };

    int cur = 0;
    int ht = blockIdx.x;
    if (ht < nHT) { LOADHT(ht); STOREHT(0); }
    __syncthreads();

    while (ht < nHT) {
        const int htn  = ht + gridDim.x;
        const int base = ht * 64;

        if (htn < nHT) LOADHT(htn);

        float acc[2][8][4];
        #pragma unroll
        for (int mb = 0; mb < 2; mb++)
            #pragma unroll
            for (int nb = 0; nb < 8; nb++)
                #pragma unroll
                for (int q = 0; q < 4; q++) acc[mb][nb][q] = 0.f;

        const uint32_t Abase = smem_base + cur * HSLAB + warp_m * 32 * ROWB + offA;
        const uint32_t Bbase = smem_base + ABUF_T + chn * SLAB + ncl * ROWB + offB;
        #pragma unroll
        for (int ks = 0; ks < 8; ks++) {
            const int kB = ks * 32;
            uint32_t a[2][4];
            ldsm4(a[0], Abase + kB);
            ldsm4(a[1], Abase + 16 * ROWB + kB);
            uint32_t b[4][4];
            #pragma unroll
            for (int pr = 0; pr < 4; pr++)
                ldsm4(b[pr], Bbase + pr * 16 * ROWB + kB);
            #pragma unroll
            for (int mb = 0; mb < 2; mb++)
                #pragma unroll
                for (int pr = 0; pr < 4; pr++) {
                    mma16816h(acc[mb][pr * 2],     a[mb], &b[pr][0]);
                    mma16816h(acc[mb][pr * 2 + 1], a[mb], &b[pr][2]);
                }
        }

        // epilogue: warp_n 0,1 -> Yt (fp32); warp_n 2,3 -> Yb (fp16)
        #pragma unroll
        for (int mb = 0; mb < 2; mb++) {
            int row0 = base + warp_m * 32 + mb * 16 + g;
            #pragma unroll
            for (int nb = 0; nb < 8; nb++) {
                int col = (warp_n & 1) * 64 + nb * 8 + tig * 2;
                if (chn == 0) {
                    if (row0 < nRows)
                        *(float2*)(Yt + (size_t)row0 * 128 + col) =
                            make_float2(acc[mb][nb][0], acc[mb][nb][1]);
                    if (row0 + 8 < nRows)
                        *(float2*)(Yt + (size_t)(row0 + 8) * 128 + col) =
                            make_float2(acc[mb][nb][2], acc[mb][nb][3]);
                } else {
                    if (row0 < nRows)
                        *(__half2*)(Yb + (size_t)row0 * 128 + col) =
                            __floats2half2_rn(acc[mb][nb][0], acc[mb][nb][1]);
                    if (row0 + 8 < nRows)
                        *(__half2*)(Yb + (size_t)(row0 + 8) * 128 + col) =
                            __floats2half2_rn(acc[mb][nb][2], acc[mb][nb][3]);
                }
            }
        }

        if (htn < nHT) STOREHT(cur ^ 1);
        __syncthreads();
        cur ^= 1;
        ht = htn;
    }
}

// ---------------- kernel 3: agg1  h1[i] = Yt[i] + mean_d Yb[nbr[i][d]] ----------------
__global__ void __launch_bounds__(256) agg1_kernel(
    const float* __restrict__ Yt, const __half* __restrict__ Yb,
    const int* __restrict__ nbr, float* __restrict__ h1, int N)
{
    int wid = threadIdx.x >> 5, lid = threadIdx.x & 31;
    int node = blockIdx.x * 8 + wid;
    if (node >= N) return;
    const int* nb = nbr + (size_t)node * DEG;
    float a0 = 0.f, a1 = 0.f, a2 = 0.f, a3 = 0.f;
    #pragma unroll
    for (int d = 0; d < DEG; d++) {
        int j = __ldg(nb + d);
        uint2 u = *(const uint2*)(Yb + (size_t)j * 128 + lid * 4);
        __half2 p0 = *reinterpret_cast<__half2*>(&u.x);
        __half2 p1 = *reinterpret_cast<__half2*>(&u.y);
        float2 f0 = __half22float2(p0);
        float2 f1 = __half22float2(p1);
        a0 += f0.x; a1 += f0.y; a2 += f1.x; a3 += f1.y;
    }
    float4 t = *(const float4*)(Yt + (size_t)node * 128 + lid * 4);
    float4 o;
    o.x = t.x + a0 * 0.0625f;
    o.y = t.y + a1 * 0.0625f;
    o.z = t.z + a2 * 0.0625f;
    o.w = t.w + a3 * 0.0625f;
    *(float4*)(h1 + (size_t)node * 128 + lid * 4) = o;
}

// ---------------- kernel 4: agg2  x2[b] = f16([h1[nodes[b]], mean(h1[nbr])]) ----------------
__global__ void __launch_bounds__(256) agg2_kernel(
    const float* __restrict__ h1, const int* __restrict__ nbr,
    const int* __restrict__ nodes, __half* __restrict__ x2, int B)
{
    int wid = threadIdx.x >> 5, lid = threadIdx.x & 31;
    int b = blockIdx.x * 8 + wid;
    if (b >= B) return;
    int self = __ldg(nodes + b);

    float4 sv = *(const float4*)(h1 + (size_t)self * 128 + lid * 4);

    const int* nb = nbr + (size_t)self * DEG;
    float a0 = 0.f, a1 = 0.f, a2 = 0.f, a3 = 0.f;
    #pragma unroll
    for (int d = 0; d < DEG; d++) {
        int j = __ldg(nb + d);
        float4 v = *(const float4*)(h1 + (size_t)j * 128 + lid * 4);
        a0 += v.x; a1 += v.y; a2 += v.z; a3 += v.w;
    }
    a0 *= 0.0625f; a1 *= 0.0625f; a2 *= 0.0625f; a3 *= 0.0625f;

    size_t base = (size_t)b * 256;
    *(uint2*)(x2 + base + lid * 4) =
        make_uint2(h2bits(__floats2half2_rn(sv.x, sv.y)),
                   h2bits(__floats2half2_rn(sv.z, sv.w)));
    *(uint2*)(x2 + base + 128 + lid * 4) =
        make_uint2(h2bits(__floats2half2_rn(a0, a1)),
                   h2bits(__floats2half2_rn(a2, a3)));
}

// ---------------- kernel 5: gemm2  out[B,128] = x2[B,256] @ (w2h + w2l) ----------------
// smem: A @ 0 ; B[lvl2] @ A2SLAB + lvl*B2SLAB
__global__ void __launch_bounds__(256, 1) gemm2_kernel(
    const __half* __restrict__ x2, float* __restrict__ out, int B)
{
    extern __shared__ unsigned char smem[];
    const int tid = threadIdx.x, wid = tid >> 5, lid = tid & 31;
    const int g   = lid >> 2, tig = lid & 3;
    const int warp_m = wid & 1, warp_n = wid >> 1;   // 2 x 32 rows, 4 x 32 cols
    const uint32_t smem_base = smem_u32(smem);
    const int base = blockIdx.x * 64;

    const int offA = ((lid & 7) + ((lid >> 3) & 1) * 8) * ROWB2 + (lid >> 4) * 16;
    const int offB = ((lid & 7) + (lid >> 4) * 8) * ROWB2 + ((lid >> 3) & 1) * 16;

    // stage B (both levels, contiguous image)
    {
        const uint4* src = (const uint4*)&g_B2img[0][0];
        uint4* dst = (uint4*)(smem + A2SLAB);
        #pragma unroll 4
        for (int i = tid; i < 2 * B2SLAB / 16; i += 256) dst[i] = src[i];
    }
    // stage A: 64 rows x 512B, pitched to 528
    {
        int r = tid >> 2, q = tid & 3;               // r 0..63, 128B quarter
        int grow = base + r;
        const uint4* sh = (const uint4*)(x2 + (size_t)grow * 256) + q * 8;
        uint4* dh = (uint4*)(smem + r * ROWB2 + q * 128);
        if (grow < B) {
            #pragma unroll
            for (int j = 0; j < 8; j++) dh[j] = sh[j];
        } else {
            uint4 z = make_uint4(0, 0, 0, 0);
            #pragma unroll
            for (int j = 0; j < 8; j++) dh[j] = z;
        }
    }
    __syncthreads();

    float acc[2][4][4];
    #pragma unroll
    for (int mb = 0; mb < 2; mb++)
        #pragma unroll
        for (int nb = 0; nb < 4; nb++)
            #pragma unroll
            for (int q = 0; q < 4; q++) acc[mb][nb][q] = 0.f;

    #pragma unroll
    for (int p = 0; p < 2; p++) {
        const uint32_t Abase = smem_base + warp_m * 32 * ROWB2 + offA;
        const uint32_t Bbase = smem_base + A2SLAB + p * B2SLAB
                             + warp_n * 32 * ROWB2 + offB;
        #pragma unroll
        for (int ks = 0; ks < 16; ks++) {
            const int kB = ks * 32;
            uint32_t a[2][4];
            ldsm4(a[0], Abase + kB);
            ldsm4(a[1], Abase + 16 * ROWB2 + kB);
            uint32_t b[2][4];
            ldsm4(b[0], Bbase + kB);
            ldsm4(b[1], Bbase + 16 * ROWB2 + kB);
            #pragma unroll
            for (int mb = 0; mb < 2; mb++)
                #pragma unroll
                for (int pr = 0; pr < 2; pr++) {
                    mma16816h(acc[mb][pr * 2],     a[mb], &b[pr][0]);
                    mma16816h(acc[mb][pr * 2 + 1], a[mb], &b[pr][2]);
                }
        }
    }

    #pragma unroll
    for (int mb = 0; mb < 2; mb++) {
        int row0 = base + warp_m * 32 + mb * 16 + g;
        #pragma unroll
        for (int nb = 0; nb < 4; nb++) {
            int col = warp_n * 32 + nb * 8 + tig * 2;
            if (row0 < B)
                *(float2*)(out + (size_t)row0 * 128 + col) =
                    make_float2(acc[mb][nb][0], acc[mb][nb][1]);
            if (row0 + 8 < B)
                *(float2*)(out + (size_t)(row0 + 8) * 128 + col) =
                    make_float2(acc[mb][nb][2], acc[mb][nb][3]);
        }
    }
}

// ---------------- host ----------------
extern "C" void kernel_launch(void* const* d_in, const int* in_sizes, int n_in,
                              void* d_out, int out_size)
{
    const float* features     = (const float*)d_in[0];
    const float* w1           = (const float*)d_in[1];
    const float* w2           = (const float*)d_in[2];
    const int*   neighbor_idx = (const int*)d_in[3];
    const int*   nodes        = (const int*)d_in[4];
    float*       out          = (float*)d_out;

    const int N = in_sizes[0] / F;
    const int B = in_sizes[4];

    float* Yt;  float* h1p;  __half* Yb;  __half* x2;
    cudaGetSymbolAddress((void**)&Yt,  g_Yt);
    cudaGetSymbolAddress((void**)&Yb,  g_Yb);
    cudaGetSymbolAddress((void**)&h1p, g_h1);
    cudaGetSymbolAddress((void**)&x2,  g_x2);

    // 1) weight images
    prep_kernel<<<256, 256>>>(w1, w2);

    // 2) gemm1: Yt / Yb for all N  (2 CTAs/SM)
    const int nHT = (N + 63) / 64;
    cudaFuncSetAttribute(gemm1_kernel, cudaFuncAttributeMaxDynamicSharedMemorySize, SMEM_G1);
    gemm1_kernel<<<296, 256, SMEM_G1>>>(features, Yt, Yb, N, nHT);

    // 3) agg1 -> h1
    agg1_kernel<<<(N + 7) / 8, 256>>>(Yt, Yb, neighbor_idx, h1p, N);

    // 4) agg2 -> x2 (fp16)
    agg2_kernel<<<(B + 7) / 8, 256>>>(h1p, neighbor_idx, nodes, x2, B);

    // 5) gemm2 -> out
    cudaFuncSetAttribute(gemm2_kernel, cudaFuncAttributeMaxDynamicSharedMemorySize, SMEM_G2);
    gemm2_kernel<<<(B + 63) / 64, 256, SMEM_G2>>>(x2, out, B);
}

// round 8
// speedup vs baseline: 3.1717x; 1.0866x over previous
#include <cuda_runtime.h>
#include <cuda_bf16.h>
#include <cuda_fp16.h>
#include <cstdint>

#define F      128
#define H      128
#define DEG    16
#define KDIM   256
#define NMAX   131072
#define BMAX   16384
#define PITCH  136            // fp16/row gemm1 (K=128); 272 B ≡ 4 words (mod 32) -> conflict-free
#define ROWB   272
#define HSLAB  (64 * ROWB)    // 17408 B  (64-row A half-slab)
#define SLAB   (128 * ROWB)   // 34816 B  (128-n B slab)
#define ABUF_T (2 * HSLAB)    // 34816 B  (A: 2 buffers)
#define SMEM_G1 (ABUF_T + 2 * SLAB)   // 104448 B -> 2 CTAs/SM

#define PITCH2 264            // fp16/row gemm2 (K=256); 528 B ≡ 4 words (mod 32)
#define ROWB2  528
#define A2SLAB (64 * ROWB2)   // 33792 B
#define B2SLAB (128 * ROWB2)  // 67584 B per lvl
#define SMEM_G2 (A2SLAB + 2 * B2SLAB)  // 168960 B

// ---------------- scratch (all intermediates fp16) ----------------
__device__ __half g_Yt[(size_t)NMAX * 128];     // f @ w1_top
__device__ __half g_Yb[(size_t)NMAX * 128];     // f @ w1_bot (gathered)
__device__ __half g_h1[(size_t)NMAX * 128];     // layer-1 embeddings
__device__ __half g_B1img[2][128 * PITCH];      // [ch][n][k]   (w1 fp16)
__device__ __half g_B2img[2][128 * PITCH2];     // [lvl][n][k]  (w2 hi/lo fp16)
__device__ __half g_x2[(size_t)BMAX * 256];     // layer2 input (fp16)

// ---------------- PTX helpers ----------------
__device__ __forceinline__ void mma16816h(float* c, const uint32_t* a, const uint32_t* b) {
    asm volatile(
        "mma.sync.aligned.m16n8k16.row.col.f32.f16.f16.f32 "
        "{%0,%1,%2,%3}, {%4,%5,%6,%7}, {%8,%9}, {%0,%1,%2,%3};"
        : "+f"(c[0]), "+f"(c[1]), "+f"(c[2]), "+f"(c[3])
        : "r"(a[0]), "r"(a[1]), "r"(a[2]), "r"(a[3]), "r"(b[0]), "r"(b[1]));
}
__device__ __forceinline__ void ldsm4(uint32_t* r, uint32_t addr) {
    asm volatile("ldmatrix.sync.aligned.m8n8.x4.shared.b16 {%0,%1,%2,%3}, [%4];"
        : "=r"(r[0]), "=r"(r[1]), "=r"(r[2]), "=r"(r[3]) : "r"(addr));
}
__device__ __forceinline__ uint32_t smem_u32(const void* p) {
    return (uint32_t)__cvta_generic_to_shared(p);
}
__device__ __forceinline__ void split_fp16(float v, __half& hi, __half& lo) {
    hi = __float2half_rn(v);
    lo = __float2half_rn(v - __half2float(hi));
}
__device__ __forceinline__ uint32_t h2bits(__half2 h) {
    return *reinterpret_cast<uint32_t*>(&h);
}

// ---------------- kernel 1: build fp16 weight images ----------------
__global__ void prep_kernel(const float* __restrict__ w1, const float* __restrict__ w2) {
    int i = blockIdx.x * 256 + threadIdx.x;          // 65536 total
    if (i < 32768) {
        int ch = i >> 14, n = (i >> 7) & 127, k = i & 127;
        float v = w1[(size_t)(ch * 128 + k) * 128 + n];
        g_B1img[ch][n * PITCH + k] = __float2half_rn(v);
    } else if (i < 65536) {
        int j = i - 32768;
        int n = j & 127, k = j >> 7;                 // k in 0..255
        float v = w2[(size_t)k * 128 + n];
        __half hb, lb;
        split_fp16(v, hb, lb);
        g_B2img[0][n * PITCH2 + k] = hb;
        g_B2img[1][n * PITCH2 + k] = lb;
    }
}

// ---------------- kernel 2: gemm1  Y[N,256] = f16(f)[N,128] @ f16(w1); all-fp16 outputs ----------------
// smem: A[buf2] @ buf*HSLAB ; B[ch2] @ ABUF_T + ch*SLAB
__global__ void __launch_bounds__(256, 2) gemm1_kernel(
    const float* __restrict__ f, __half* __restrict__ Yt, __half* __restrict__ Yb,
    int nRows, int nHT)
{
    extern __shared__ unsigned char smem[];
    const int tid = threadIdx.x, wid = tid >> 5, lid = tid & 31;
    const int g   = lid >> 2, tig = lid & 3;
    const int warp_m = wid & 1, warp_n = wid >> 1;       // 2 x 32 rows, 4 x 64 cols
    const int chn = warp_n >> 1, ncl = (warp_n & 1) * 64;
    const uint32_t smem_base = smem_u32(smem);

    const int offA = ((lid & 7) + ((lid >> 3) & 1) * 8) * ROWB + (lid >> 4) * 16;
    const int offB = ((lid & 7) + (lid >> 4) * 8) * ROWB + ((lid >> 3) & 1) * 16;

    // stage both B slabs (g_B1img contiguous [ch])
    {
        const uint4* src = (const uint4*)&g_B1img[0][0];
        uint4* dst = (uint4*)(smem + ABUF_T);
        #pragma unroll 4
        for (int i = tid; i < 2 * SLAB / 16; i += 256) dst[i] = src[i];
    }

    const int r_st = tid >> 5;          // row in 8-row group
    const int k_st = (tid & 31) * 4;    // k0 elements

    float4 Rst[8];
    auto LOADHT = [&](int ht) {
        const int base = ht * 64;
        #pragma unroll
        for (int j = 0; j < 8; j++) {
            int grow = base + j * 8 + r_st;
            Rst[j] = (grow < nRows) ? *(const float4*)(f + (size_t)grow * 128 + k_st)
                                    : make_float4(0.f, 0.f, 0.f, 0.f);
        }
    };
    auto STOREHT = [&](int buf) {
        unsigned char* Ah = smem + buf * HSLAB;
        #pragma unroll
        for (int j = 0; j < 8; j++) {
            uint2 u;
            u.x = h2bits(__floats2half2_rn(Rst[j].x, Rst[j].y));
            u.y = h2bits(__floats2half2_rn(Rst[j].z, Rst[j].w));
            int r = j * 8 + r_st;
            *(uint2*)(Ah + r * ROWB + k_st * 2) = u;
        }
    };

    int cur = 0;
    int ht = blockIdx.x;
    if (ht < nHT) { LOADHT(ht); STOREHT(0); }
    __syncthreads();

    while (ht < nHT) {
        const int htn  = ht + gridDim.x;
        const int base = ht * 64;

        if (htn < nHT) LOADHT(htn);

        float acc[2][8][4];
        #pragma unroll
        for (int mb = 0; mb < 2; mb++)
            #pragma unroll
            for (int nb = 0; nb < 8; nb++)
                #pragma unroll
                for (int q = 0; q < 4; q++) acc[mb][nb][q] = 0.f;

        const uint32_t Abase = smem_base + cur * HSLAB + warp_m * 32 * ROWB + offA;
        const uint32_t Bbase = smem_base + ABUF_T + chn * SLAB + ncl * ROWB + offB;
        #pragma unroll
        for (int ks = 0; ks < 8; ks++) {
            const int kB = ks * 32;
            uint32_t a[2][4];
            ldsm4(a[0], Abase + kB);
            ldsm4(a[1], Abase + 16 * ROWB + kB);
            uint32_t b[4][4];
            #pragma unroll
            for (int pr = 0; pr < 4; pr++)
                ldsm4(b[pr], Bbase + pr * 16 * ROWB + kB);
            #pragma unroll
            for (int mb = 0; mb < 2; mb++)
                #pragma unroll
                for (int pr = 0; pr < 4; pr++) {
                    mma16816h(acc[mb][pr * 2],     a[mb], &b[pr][0]);
                    mma16816h(acc[mb][pr * 2 + 1], a[mb], &b[pr][2]);
                }
        }

        // epilogue: warp_n 0,1 -> Yt; warp_n 2,3 -> Yb (both fp16)
        __half* dst = (chn == 0) ? Yt : Yb;
        #pragma unroll
        for (int mb = 0; mb < 2; mb++) {
            int row0 = base + warp_m * 32 + mb * 16 + g;
            #pragma unroll
            for (int nb = 0; nb < 8; nb++) {
                int col = (warp_n & 1) * 64 + nb * 8 + tig * 2;
                if (row0 < nRows)
                    *(__half2*)(dst + (size_t)row0 * 128 + col) =
                        __floats2half2_rn(acc[mb][nb][0], acc[mb][nb][1]);
                if (row0 + 8 < nRows)
                    *(__half2*)(dst + (size_t)(row0 + 8) * 128 + col) =
                        __floats2half2_rn(acc[mb][nb][2], acc[mb][nb][3]);
            }
        }

        if (htn < nHT) STOREHT(cur ^ 1);
        __syncthreads();
        cur ^= 1;
        ht = htn;
    }
}

// ---------------- kernel 3: agg1  h1[i] = f16(Yt[i] + mean_d Yb[nbr[i][d]]) ----------------
__global__ void __launch_bounds__(256) agg1_kernel(
    const __half* __restrict__ Yt, const __half* __restrict__ Yb,
    const int* __restrict__ nbr, __half* __restrict__ h1, int N)
{
    int wid = threadIdx.x >> 5, lid = threadIdx.x & 31;
    int node = blockIdx.x * 8 + wid;
    if (node >= N) return;
    const int* nb = nbr + (size_t)node * DEG;
    float a0 = 0.f, a1 = 0.f, a2 = 0.f, a3 = 0.f;
    #pragma unroll
    for (int d = 0; d < DEG; d++) {
        int j = __ldg(nb + d);
        uint2 u = *(const uint2*)(Yb + (size_t)j * 128 + lid * 4);
        float2 f0 = __half22float2(*reinterpret_cast<__half2*>(&u.x));
        float2 f1 = __half22float2(*reinterpret_cast<__half2*>(&u.y));
        a0 += f0.x; a1 += f0.y; a2 += f1.x; a3 += f1.y;
    }
    uint2 t = *(const uint2*)(Yt + (size_t)node * 128 + lid * 4);
    float2 t0 = __half22float2(*reinterpret_cast<__half2*>(&t.x));
    float2 t1 = __half22float2(*reinterpret_cast<__half2*>(&t.y));
    uint2 o;
    o.x = h2bits(__floats2half2_rn(t0.x + a0 * 0.0625f, t0.y + a1 * 0.0625f));
    o.y = h2bits(__floats2half2_rn(t1.x + a2 * 0.0625f, t1.y + a3 * 0.0625f));
    *(uint2*)(h1 + (size_t)node * 128 + lid * 4) = o;
}

// ---------------- kernel 4: agg2  x2[b] = [h1[nodes[b]], f16(mean(h1[nbr]))] ----------------
__global__ void __launch_bounds__(256) agg2_kernel(
    const __half* __restrict__ h1, const int* __restrict__ nbr,
    const int* __restrict__ nodes, __half* __restrict__ x2, int B)
{
    int wid = threadIdx.x >> 5, lid = threadIdx.x & 31;
    int b = blockIdx.x * 8 + wid;
    if (b >= B) return;
    int self = __ldg(nodes + b);

    uint2 sv = *(const uint2*)(h1 + (size_t)self * 128 + lid * 4);   // bit-copy self half

    const int* nb = nbr + (size_t)self * DEG;
    float a0 = 0.f, a1 = 0.f, a2 = 0.f, a3 = 0.f;
    #pragma unroll
    for (int d = 0; d < DEG; d++) {
        int j = __ldg(nb + d);
        uint2 u = *(const uint2*)(h1 + (size_t)j * 128 + lid * 4);
        float2 f0 = __half22float2(*reinterpret_cast<__half2*>(&u.x));
        float2 f1 = __half22float2(*reinterpret_cast<__half2*>(&u.y));
        a0 += f0.x; a1 += f0.y; a2 += f1.x; a3 += f1.y;
    }
    a0 *= 0.0625f; a1 *= 0.0625f; a2 *= 0.0625f; a3 *= 0.0625f;

    size_t base = (size_t)b * 256;
    *(uint2*)(x2 + base + lid * 4) = sv;
    *(uint2*)(x2 + base + 128 + lid * 4) =
        make_uint2(h2bits(__floats2half2_rn(a0, a1)),
                   h2bits(__floats2half2_rn(a2, a3)));
}

// ---------------- kernel 5: gemm2  out[B,128] = x2[B,256] @ (w2h + w2l) ----------------
// smem: A @ 0 ; B[lvl2] @ A2SLAB + lvl*B2SLAB
__global__ void __launch_bounds__(256, 1) gemm2_kernel(
    const __half* __restrict__ x2, float* __restrict__ out, int B)
{
    extern __shared__ unsigned char smem[];
    const int tid = threadIdx.x, wid = tid >> 5, lid = tid & 31;
    const int g   = lid >> 2, tig = lid & 3;
    const int warp_m = wid & 1, warp_n = wid >> 1;   // 2 x 32 rows, 4 x 32 cols
    const uint32_t smem_base = smem_u32(smem);
    const int base = blockIdx.x * 64;

    const int offA = ((lid & 7) + ((lid >> 3) & 1) * 8) * ROWB2 + (lid >> 4) * 16;
    const int offB = ((lid & 7) + (lid >> 4) * 8) * ROWB2 + ((lid >> 3) & 1) * 16;

    // stage B (both levels, contiguous image)
    {
        const uint4* src = (const uint4*)&g_B2img[0][0];
        uint4* dst = (uint4*)(smem + A2SLAB);
        #pragma unroll 4
        for (int i = tid; i < 2 * B2SLAB / 16; i += 256) dst[i] = src[i];
    }
    // stage A: 64 rows x 512B, pitched to 528
    {
        int r = tid >> 2, q = tid & 3;               // r 0..63, 128B quarter
        int grow = base + r;
        const uint4* sh = (const uint4*)(x2 + (size_t)grow * 256) + q * 8;
        uint4* dh = (uint4*)(smem + r * ROWB2 + q * 128);
        if (grow < B) {
            #pragma unroll
            for (int j = 0; j < 8; j++) dh[j] = sh[j];
        } else {
            uint4 z = make_uint4(0, 0, 0, 0);
            #pragma unroll
            for (int j = 0; j < 8; j++) dh[j] = z;
        }
    }
    __syncthreads();

    float acc[2][4][4];
    #pragma unroll
    for (int mb = 0; mb < 2; mb++)
        #pragma unroll
        for (int nb = 0; nb < 4; nb++)
            #pragma unroll
            for (int q = 0; q < 4; q++) acc[mb][nb][q] = 0.f;

    #pragma unroll
    for (int p = 0; p < 2; p++) {
        const uint32_t Abase = smem_base + warp_m * 32 * ROWB2 + offA;
        const uint32_t Bbase = smem_base + A2SLAB + p * B2SLAB
                             + warp_n * 32 * ROWB2 + offB;
        #pragma unroll
        for (int ks = 0; ks < 16; ks++) {
            const int kB = ks * 32;
            uint32_t a[2][4];
            ldsm4(a[0], Abase + kB);
            ldsm4(a[1], Abase + 16 * ROWB2 + kB);
            uint32_t b[2][4];
            ldsm4(b[0], Bbase + kB);
            ldsm4(b[1], Bbase + 16 * ROWB2 + kB);
            #pragma unroll
            for (int mb = 0; mb < 2; mb++)
                #pragma unroll
                for (int pr = 0; pr < 2; pr++) {
                    mma16816h(acc[mb][pr * 2],     a[mb], &b[pr][0]);
                    mma16816h(acc[mb][pr * 2 + 1], a[mb], &b[pr][2]);
                }
        }
    }

    #pragma unroll
    for (int mb = 0; mb < 2; mb++) {
        int row0 = base + warp_m * 32 + mb * 16 + g;
        #pragma unroll
        for (int nb = 0; nb < 4; nb++) {
            int col = warp_n * 32 + nb * 8 + tig * 2;
            if (row0 < B)
                *(float2*)(out + (size_t)row0 * 128 + col) =
                    make_float2(acc[mb][nb][0], acc[mb][nb][1]);
            if (row0 + 8 < B)
                *(float2*)(out + (size_t)(row0 + 8) * 128 + col) =
                    make_float2(acc[mb][nb][2], acc[mb][nb][3]);
        }
    }
}

// ---------------- host ----------------
extern "C" void kernel_launch(void* const* d_in, const int* in_sizes, int n_in,
                              void* d_out, int out_size)
{
    const float* features     = (const float*)d_in[0];
    const float* w1           = (const float*)d_in[1];
    const float* w2           = (const float*)d_in[2];
    const int*   neighbor_idx = (const int*)d_in[3];
    const int*   nodes        = (const int*)d_in[4];
    float*       out          = (float*)d_out;

    const int N = in_sizes[0] / F;
    const int B = in_sizes[4];

    __half *Yt, *Yb, *h1p, *x2;
    cudaGetSymbolAddress((void**)&Yt,  g_Yt);
    cudaGetSymbolAddress((void**)&Yb,  g_Yb);
    cudaGetSymbolAddress((void**)&h1p, g_h1);
    cudaGetSymbolAddress((void**)&x2,  g_x2);

    // 1) weight images
    prep_kernel<<<256, 256>>>(w1, w2);

    // 2) gemm1: Yt / Yb for all N  (2 CTAs/SM)
    const int nHT = (N + 63) / 64;
    cudaFuncSetAttribute(gemm1_kernel, cudaFuncAttributeMaxDynamicSharedMemorySize, SMEM_G1);
    gemm1_kernel<<<296, 256, SMEM_G1>>>(features, Yt, Yb, N, nHT);

    // 3) agg1 -> h1 (fp16)
    agg1_kernel<<<(N + 7) / 8, 256>>>(Yt, Yb, neighbor_idx, h1p, N);

    // 4) agg2 -> x2 (fp16)
    agg2_kernel<<<(B + 7) / 8, 256>>>(h1p, neighbor_idx, nodes, x2, B);

    // 5) gemm2 -> out
    cudaFuncSetAttribute(gemm2_kernel, cudaFuncAttributeMaxDynamicSharedMemorySize, SMEM_G2);
    gemm2_kernel<<<(B + 63) / 64, 256, SMEM_G2>>>(x2, out, B);
}